// round 13
// baseline (speedup 1.0000x reference)
#include <cuda_runtime.h>
#include <cuda_fp16.h>
#include <math.h>
#include <float.h>
#include <stdint.h>

// Problem constants
#define BB 2
#define NN 4096
#define KNBR 20
#define NPTS (BB*NN)            // 8192
#define NROWS (NPTS*KNBR)       // 163840
#define C1 128
#define C2 256
#define C3 512
#define CH 384
#define BN_EPS 1e-5f
#define STAT_BLOCKS 1024
#define ROWS_PER_STAT (NROWS/STAT_BLOCKS) // 160

__device__ __forceinline__ void cp16(void* dst, const void* src) {
    uint32_t s = (uint32_t)__cvta_generic_to_shared(dst);
    asm volatile("cp.async.cg.shared.global [%0], [%1], 16;" :: "r"(s), "l"(src));
}
#define CP_COMMIT() asm volatile("cp.async.commit_group;" ::: "memory")
#define CP_WAIT(n)  asm volatile("cp.async.wait_group %0;" :: "n"(n) : "memory")

__device__ __forceinline__ uint32_t pack_h2(float a, float b) {
    __half2 h = __floats2half2_rn(a, b);
    return *(uint32_t*)&h;
}

// ldmatrix x4 (A fragments, non-transposed)
__device__ __forceinline__ void ldsm4(uint32_t* r, uint32_t saddr) {
    asm volatile("ldmatrix.sync.aligned.m8n8.x4.shared.b16 {%0,%1,%2,%3}, [%4];"
        : "=r"(r[0]), "=r"(r[1]), "=r"(r[2]), "=r"(r[3]) : "r"(saddr));
}
// ldmatrix x4 transposed (B fragments from [k][n] row-major smem)
__device__ __forceinline__ void ldsm4t(uint32_t* r, uint32_t saddr) {
    asm volatile("ldmatrix.sync.aligned.m8n8.x4.trans.shared.b16 {%0,%1,%2,%3}, [%4];"
        : "=r"(r[0]), "=r"(r[1]), "=r"(r[2]), "=r"(r[3]) : "r"(saddr));
}

// order-preserving float<->uint for atomicMax
__device__ __forceinline__ unsigned fenc(float f) {
    int b = __float_as_int(f);
    return (b < 0) ? ~((unsigned)b) : (((unsigned)b) | 0x80000000u);
}
__device__ __forceinline__ float fdec(unsigned k) {
    return (k & 0x80000000u) ? __int_as_float((int)(k ^ 0x80000000u))
                             : __int_as_float((int)(~k));
}

// bn3+relu on an fp16x2 fragment in half2 math (HFMA2 + HMAX2)
__device__ __forceinline__ uint32_t bnfrag_h2(uint32_t a, uint32_t sc2, uint32_t sh2) {
    __half2 r = __hfma2(*(__half2*)&a, *(__half2*)&sc2, *(__half2*)&sh2);
    r = __hmax2(r, __float2half2_rn(0.f));
    return *(uint32_t*)&r;
}

// ---------------- scratch (static device globals) ----------------
__device__ int      g_idx[NROWS];
__device__ float    g_part1[STAT_BLOCKS*2*C1];
__device__ float    g_ss1[2*C1];
__device__ __half   g_Ah[(size_t)NROWS*C1];      // 42 MB
__device__ __half   g_H2h[(size_t)NROWS*C2];     // 84 MB
__device__ __half   g_gmaxh[(size_t)NPTS*C2];
__device__ float    g_fA[(size_t)NPTS*C3];
__device__ __half   g_fpreh[(size_t)NROWS*C3];   // 168 MB
__device__ float    g_p3[(size_t)(NROWS/128)*2*C3];
__device__ float    g_ss3[2*C3];
__device__ uint32_t g_ss3h[2*(C3/2)];            // half2-packed: [sc 256][sh 256]
__device__ __half   g_w3hh[256*C3];              // W3[256:512] fp16 [k][col]
__device__ __half   g_w4hh[C3*CH];               // W4 fp16 [k][col]

// ---------------------------------------------------------------------------
// K1: KNN (unchanged — passing, R9)
// ---------------------------------------------------------------------------
__global__ void knn_kernel(const float* __restrict__ xyz) {
    __shared__ float sd[NN];
    __shared__ float rv[8];
    __shared__ int   ri8[8];
    __shared__ int   swin;
    int p = blockIdx.x;
    int b = p >> 12, n = p & (NN-1);
    int t = threadIdx.x, lane = t & 31, w = t >> 5;
    const float* base = xyz + (size_t)b*NN*3;
    float cx = base[n*3+0], cy = base[n*3+1], cz = base[n*3+2];
    float pp = cx*cx + cy*cy + cz*cz;
    float bv = FLT_MAX; int bi = NN;
    for (int m = t; m < NN; m += 256) {
        float qx = base[m*3+0], qy = base[m*3+1], qz = base[m*3+2];
        float d2 = pp + (qx*qx + qy*qy + qz*qz) - 2.f*(cx*qx + cy*qy + cz*qz);
        sd[m] = d2;
        if (d2 < bv) { bv = d2; bi = m; }
    }
    __syncthreads();
    for (int round = 0; round < KNBR; ++round) {
        float rb = bv; int rx = bi;
        #pragma unroll
        for (int off = 16; off > 0; off >>= 1) {
            float ov = __shfl_down_sync(0xffffffffu, rb, off);
            int   oi = __shfl_down_sync(0xffffffffu, rx, off);
            if (ov < rb || (ov == rb && oi < rx)) { rb = ov; rx = oi; }
        }
        if (lane == 0) { rv[w] = rb; ri8[w] = rx; }
        __syncthreads();
        if (w == 0) {
            float v2 = (lane < 8) ? rv[lane] : FLT_MAX;
            int   i2 = (lane < 8) ? ri8[lane] : NN;
            #pragma unroll
            for (int off = 4; off > 0; off >>= 1) {
                float ov = __shfl_down_sync(0xffffffffu, v2, off);
                int   oi = __shfl_down_sync(0xffffffffu, i2, off);
                if (ov < v2 || (ov == v2 && oi < i2)) { v2 = ov; i2 = oi; }
            }
            if (lane == 0) {
                g_idx[p*KNBR + round] = i2;
                sd[i2] = FLT_MAX;
                swin = i2;
            }
        }
        __syncthreads();
        if (bi == swin) {
            bv = FLT_MAX; bi = NN;
            for (int m = t; m < NN; m += 256) {
                float v = sd[m];
                if (v < bv) { bv = v; bi = m; }
            }
        }
    }
}

// ---------------------------------------------------------------------------
// BN1 stats (unchanged)
// ---------------------------------------------------------------------------
__global__ void stats1_kernel(const float* __restrict__ xyz,
                              const float* __restrict__ W1,
                              const float* __restrict__ b1) {
    __shared__ float se[ROWS_PER_STAT*6];
    int blk = blockIdx.x, t = threadIdx.x;
    int row0 = blk * ROWS_PER_STAT;
    for (int r = t; r < ROWS_PER_STAT; r += 128) {
        int gr = row0 + r;
        int p  = gr / KNBR;
        int b  = p >> 12, n = p & (NN-1);
        int id = g_idx[gr];
        const float* cb = xyz + ((size_t)b*NN + n)*3;
        const float* nb = xyz + ((size_t)b*NN + id)*3;
        se[r*6+0] = nb[0]-cb[0];
        se[r*6+1] = nb[1]-cb[1];
        se[r*6+2] = nb[2]-cb[2];
        se[r*6+3] = cb[0]; se[r*6+4] = cb[1]; se[r*6+5] = cb[2];
    }
    __syncthreads();
    float w0 = W1[0*C1+t], w1 = W1[1*C1+t], w2 = W1[2*C1+t],
          w3 = W1[3*C1+t], w4 = W1[4*C1+t], w5 = W1[5*C1+t], bb = b1[t];
    float s = 0.f, q = 0.f;
    for (int r = 0; r < ROWS_PER_STAT; ++r) {
        float h = bb + se[r*6+0]*w0 + se[r*6+1]*w1 + se[r*6+2]*w2
                     + se[r*6+3]*w3 + se[r*6+4]*w4 + se[r*6+5]*w5;
        s += h; q += h*h;
    }
    g_part1[blk*(2*C1) + t]      = s;
    g_part1[blk*(2*C1) + C1 + t] = q;
}

__global__ void fin1_kernel(const float* __restrict__ g1,
                            const float* __restrict__ be1) {
    int c = threadIdx.x;
    float s = 0.f, q = 0.f;
    for (int i = 0; i < STAT_BLOCKS; ++i) {
        s += g_part1[i*(2*C1)+c];
        q += g_part1[i*(2*C1)+C1+c];
    }
    float mu  = s / (float)NROWS;
    float var = q / (float)NROWS - mu*mu;
    float sc  = g1[c] * rsqrtf(var + BN_EPS);
    g_ss1[c]     = sc;
    g_ss1[C1+c]  = be1[c] - mu*sc;
}

// ---------------------------------------------------------------------------
// edge16: writes fp16 A (unchanged)
// ---------------------------------------------------------------------------
__global__ __launch_bounds__(256) void edge_kernel(
    const float* __restrict__ xyz,
    const float* __restrict__ W1, const float* __restrict__ b1) {
    __shared__ float sE[16*6];
    int row0 = blockIdx.x * 16, t = threadIdx.x;
    if (t < 96) {
        int r = t / 6, d = t - r*6;
        int row = row0 + r;
        int p = row / KNBR;
        int b = p >> 12, n = p & (NN-1);
        float v;
        if (d < 3) {
            int id = g_idx[row];
            v = xyz[((size_t)b*NN + id)*3 + d] - xyz[((size_t)b*NN + n)*3 + d];
        } else {
            v = xyz[((size_t)b*NN + n)*3 + (d-3)];
        }
        sE[r*6 + d] = v;
    }
    __syncthreads();
    int c = t & (C1-1), h = t >> 7;
    float w0 = W1[0*C1+c], w1 = W1[1*C1+c], w2 = W1[2*C1+c],
          w3 = W1[3*C1+c], w4 = W1[4*C1+c], w5 = W1[5*C1+c];
    float bb = b1[c], sc = g_ss1[c], sh = g_ss1[C1+c];
    #pragma unroll
    for (int rr = 0; rr < 8; ++rr) {
        int r = h*8 + rr;
        float hv = bb + sE[r*6+0]*w0 + sE[r*6+1]*w1 + sE[r*6+2]*w2
                      + sE[r*6+3]*w3 + sE[r*6+4]*w4 + sE[r*6+5]*w5;
        hv = fmaxf(hv*sc + sh, 0.f);
        g_Ah[(size_t)(row0 + r)*C1 + c] = __float2half_rn(hv);
    }
}

// ---------------------------------------------------------------------------
// weight prep: plain fp16 [k][col]
// ---------------------------------------------------------------------------
__global__ void w3h_kernel(const float* __restrict__ W3) {
    int i = blockIdx.x*256 + threadIdx.x;
    if (i < 256*C3) {
        int k = i / C3, col = i - k*C3;
        g_w3hh[i] = __float2half_rn(W3[(size_t)(C2 + k)*C3 + col]);
    }
}
__global__ void w4h_kernel(const float* __restrict__ W4) {
    int i = blockIdx.x*256 + threadIdx.x;
    if (i < C3*CH) g_w4hh[i] = __float2half_rn(W4[i]);
}

// ===========================================================================
// fp16 m16n8k16 tile configs.
// A smem: uint32 half2 [row][kpair], stride SAH=20 u32 (ldmatrix-friendly).
// B smem (big GEMMs): fp16 [k][col], stride 72 halves (144 B) — the 8 row
// addresses of an ldmatrix tile land on 8 distinct 16B slots mod 128B.
// ===========================================================================
#define GM_MT 128
#define GM_MT2 256
#define GM_NT 64
#define GM_KC 32
#define SAH 20
#define SBH 72          // u32 stride for gemm2/gemmFA packed-word B
#define SBHH 72         // half stride for big-GEMM [k][col] B
#define A_BUFH  (GM_MT*SAH)     // 2560 u32
#define A_BUFH2 (GM_MT2*SAH)    // 5120 u32
#define B_BUFH  (16*SBH)        // 1152 u32 (gemm2/gemmFA)
#define B_BUFHH (GM_KC*SBHH/2)  // 1152 u32 (= 2304 halves, big GEMMs)

#define MMA_F16(acc, af, bf) \
    asm volatile( \
        "mma.sync.aligned.m16n8k16.row.col.f32.f16.f16.f32 " \
        "{%0,%1,%2,%3}, {%4,%5,%6,%7}, {%8,%9}, {%0,%1,%2,%3};" \
        : "+f"((acc)[0]), "+f"((acc)[1]), "+f"((acc)[2]), "+f"((acc)[3]) \
        : "r"((af)[0]), "r"((af)[1]), "r"((af)[2]), "r"((af)[3]), \
          "r"((bf)[0]), "r"((bf)[1]))

// ---------------------------------------------------------------------------
// gemm2: H2 = A @ W2 + b2 (fp16 in, fp16 out). CTA 128x64. (unchanged)
// ---------------------------------------------------------------------------
__global__ __launch_bounds__(128) void gemm2_kernel(
    const float* __restrict__ W2, const float* __restrict__ b2) {
    __shared__ __align__(16) uint32_t sA[GM_MT*SAH];
    __shared__ __align__(16) uint32_t sB[16*SBH];
    int t = threadIdx.x;
    int w = t >> 5, lane = t & 31;
    int g = lane >> 2, tig = lane & 3;
    size_t row0 = (size_t)blockIdx.y * GM_MT;
    int n0 = blockIdx.x * GM_NT;

    float acc[2][8][4] = {};

    for (int kk = 0; kk < C1; kk += GM_KC) {
        #pragma unroll
        for (int pq = 0; pq < 4; ++pq) {
            int r = pq*32 + (t>>2), seg = t&3;
            uint4 v = *(const uint4*)(g_Ah + (row0 + r)*C1 + kk + seg*8);
            *(uint4*)&sA[r*SAH + seg*4] = v;
        }
        #pragma unroll
        for (int pq = 0; pq < 2; ++pq) {
            int kp = pq*8 + (t>>4), colb = (t&15)*4;
            const float* s0 = &W2[(size_t)(kk + 2*kp)*C2 + n0 + colb];
            float4 va = *(const float4*)s0;
            float4 vb = *(const float4*)(s0 + C2);
            uint4 o = make_uint4(pack_h2(va.x, vb.x), pack_h2(va.y, vb.y),
                                 pack_h2(va.z, vb.z), pack_h2(va.w, vb.w));
            *(uint4*)&sB[kp*SBH + colb] = o;
        }
        __syncthreads();
        #pragma unroll
        for (int ks = 0; ks < 2; ++ks) {
            int kb = ks*8;
            uint32_t bf[8][2];
            #pragma unroll
            for (int n = 0; n < 8; ++n) {
                bf[n][0] = sB[(kb+tig)*SBH   + n*8 + g];
                bf[n][1] = sB[(kb+tig+4)*SBH + n*8 + g];
            }
            #pragma unroll
            for (int m = 0; m < 2; ++m) {
                int mr = w*32 + m*16;
                uint32_t af[4];
                af[0] = sA[(mr+g)*SAH   + kb + tig];
                af[1] = sA[(mr+g+8)*SAH + kb + tig];
                af[2] = sA[(mr+g)*SAH   + kb + tig + 4];
                af[3] = sA[(mr+g+8)*SAH + kb + tig + 4];
                #pragma unroll
                for (int n = 0; n < 8; ++n) MMA_F16(acc[m][n], af, bf[n]);
            }
        }
        __syncthreads();
    }
    uint32_t* H2v = (uint32_t*)g_H2h;
    #pragma unroll
    for (int m = 0; m < 2; ++m) {
        size_t r0 = row0 + w*32 + m*16 + g;
        #pragma unroll
        for (int n = 0; n < 8; ++n) {
            int col = n0 + n*8 + 2*tig;
            float2 bb = *(const float2*)&b2[col];
            H2v[r0*(C2/2) + col/2]     = pack_h2(acc[m][n][0]+bb.x, acc[m][n][1]+bb.y);
            H2v[(r0+8)*(C2/2) + col/2] = pack_h2(acc[m][n][2]+bb.x, acc[m][n][3]+bb.y);
        }
    }
}

// ---------------------------------------------------------------------------
// gmax over fp16 pairs (unchanged)
// ---------------------------------------------------------------------------
__global__ void gmax_kernel() {
    int p = blockIdx.x, t = threadIdx.x;   // 128 threads
    const __half2* src = (const __half2*)g_H2h + (size_t)p*KNBR*(C2/2) + t;
    __half2 m = src[0];
    #pragma unroll
    for (int r = 1; r < KNBR; ++r) m = __hmax2(m, src[(size_t)r*(C2/2)]);
    ((__half2*)g_gmaxh)[(size_t)p*(C2/2) + t] = m;
}

// ---------------------------------------------------------------------------
// gemmFA: fA = gmax @ W3[0:256] + b3 (unchanged)
// ---------------------------------------------------------------------------
__global__ __launch_bounds__(128) void gemmFA_kernel(
    const float* __restrict__ W3, const float* __restrict__ b3) {
    __shared__ __align__(16) uint32_t sA[GM_MT*SAH];
    __shared__ __align__(16) uint32_t sB[16*SBH];
    int t = threadIdx.x;
    int w = t >> 5, lane = t & 31;
    int g = lane >> 2, tig = lane & 3;
    size_t row0 = (size_t)blockIdx.y * GM_MT;
    int n0 = blockIdx.x * GM_NT;

    float acc[2][8][4] = {};

    for (int kk = 0; kk < C2; kk += GM_KC) {
        #pragma unroll
        for (int pq = 0; pq < 4; ++pq) {
            int r = pq*32 + (t>>2), seg = t&3;
            uint4 v = *(const uint4*)(g_gmaxh + (row0 + r)*C2 + kk + seg*8);
            *(uint4*)&sA[r*SAH + seg*4] = v;
        }
        #pragma unroll
        for (int pq = 0; pq < 2; ++pq) {
            int kp = pq*8 + (t>>4), colb = (t&15)*4;
            const float* s0 = &W3[(size_t)(kk + 2*kp)*C3 + n0 + colb];
            float4 va = *(const float4*)s0;
            float4 vb = *(const float4*)(s0 + C3);
            uint4 o = make_uint4(pack_h2(va.x, vb.x), pack_h2(va.y, vb.y),
                                 pack_h2(va.z, vb.z), pack_h2(va.w, vb.w));
            *(uint4*)&sB[kp*SBH + colb] = o;
        }
        __syncthreads();
        #pragma unroll
        for (int ks = 0; ks < 2; ++ks) {
            int kb = ks*8;
            uint32_t bf[8][2];
            #pragma unroll
            for (int n = 0; n < 8; ++n) {
                bf[n][0] = sB[(kb+tig)*SBH   + n*8 + g];
                bf[n][1] = sB[(kb+tig+4)*SBH + n*8 + g];
            }
            #pragma unroll
            for (int m = 0; m < 2; ++m) {
                int mr = w*32 + m*16;
                uint32_t af[4];
                af[0] = sA[(mr+g)*SAH   + kb + tig];
                af[1] = sA[(mr+g+8)*SAH + kb + tig];
                af[2] = sA[(mr+g)*SAH   + kb + tig + 4];
                af[3] = sA[(mr+g+8)*SAH + kb + tig + 4];
                #pragma unroll
                for (int n = 0; n < 8; ++n) MMA_F16(acc[m][n], af, bf[n]);
            }
        }
        __syncthreads();
    }
    #pragma unroll
    for (int m = 0; m < 2; ++m) {
        size_t r0 = row0 + w*32 + m*16 + g;
        #pragma unroll
        for (int n = 0; n < 8; ++n) {
            int col = n0 + n*8 + 2*tig;
            float2 bb = *(const float2*)&b3[col];
            *(float2*)&g_fA[r0*C3 + col]     = make_float2(acc[m][n][0]+bb.x, acc[m][n][1]+bb.y);
            *(float2*)&g_fA[(r0+8)*C3 + col] = make_float2(acc[m][n][2]+bb.x, acc[m][n][3]+bb.y);
        }
    }
}

// ---------------------------------------------------------------------------
// big-GEMM load helpers ([k][col] fp16 B staging)
// ---------------------------------------------------------------------------
__device__ __forceinline__ void g3_load(uint32_t* A, __half* Bh,
                                        size_t row0, int n0, int kk, int t) {
    #pragma unroll
    for (int pq = 0; pq < 8; ++pq) {
        int r = pq*32 + (t>>2), seg = t&3;
        cp16(&A[r*SAH + seg*4], g_H2h + (row0 + r)*C2 + kk + seg*8);
    }
    #pragma unroll
    for (int pass = 0; pass < 2; ++pass) {
        int idx = pass*128 + t;
        int r = idx >> 3, s = idx & 7;
        cp16(&Bh[r*SBHH + s*8], &g_w3hh[(size_t)(kk + r)*C3 + n0 + s*8]);
    }
}
__device__ __forceinline__ void g4_load(uint32_t* A, __half* Bh,
                                        size_t row0, int n0, int kk, int t) {
    #pragma unroll
    for (int pq = 0; pq < 8; ++pq) {
        int r = pq*32 + (t>>2), seg = t&3;
        cp16(&A[r*SAH + seg*4], g_fpreh + (row0 + r)*C3 + kk + seg*8);
    }
    #pragma unroll
    for (int pass = 0; pass < 2; ++pass) {
        int idx = pass*128 + t;
        int r = idx >> 3, s = idx & 7;
        cp16(&Bh[r*SBHH + s*8], &g_w4hh[(size_t)(kk + r)*CH + n0 + s*8]);
    }
}

// ---------------------------------------------------------------------------
// gemm3 (3-stage cp.async, CTA 256x64, ldmatrix A + ldmatrix.trans B,
// fused BN3-stat partials)
// ---------------------------------------------------------------------------
#define G3_SMEM ((3*A_BUFH2 + 3*B_BUFHH + 512)*4)
__global__ __launch_bounds__(128) void gemm3_kernel() {
    extern __shared__ __align__(16) uint32_t dyn[];
    uint32_t* bufA = dyn;                          // 3 x A_BUFH2
    __half*  bufB = (__half*)(dyn + 3*A_BUFH2);    // 3 x 2304 halves
    float* sstat = (float*)(dyn + 3*A_BUFH2 + 3*B_BUFHH);
    int t = threadIdx.x;
    int w = t >> 5, lane = t & 31;
    int g = lane >> 2, tig = lane & 3;
    int roff = lane & 15, koff = (lane >> 4) * 4;
    int btile = lane >> 3, brw = lane & 7;         // ldmatrix.trans lane map
    size_t row0 = (size_t)blockIdx.y * GM_MT2;
    int n0 = blockIdx.x * GM_NT;
    uint32_t sbA0 = (uint32_t)__cvta_generic_to_shared(bufA);
    uint32_t sbB0 = (uint32_t)__cvta_generic_to_shared(bufB);
    uint32_t bln = ((btile&1)*8 + brw)*(SBHH*2) + (btile>>1)*16;  // byte offset

    float acc[4][8][4] = {};
    const int NC = C2/GM_KC;  // 8

    g3_load(bufA, bufB, row0, n0, 0, t);                        CP_COMMIT();
    g3_load(bufA + A_BUFH2, bufB + 2*B_BUFHH, row0, n0, 32, t); CP_COMMIT();

    for (int c = 0; c < NC; ++c) {
        int cur = c % 3;
        if (c + 2 < NC) {
            int st = (c+2) % 3;
            g3_load(bufA + st*A_BUFH2, bufB + st*2*B_BUFHH, row0, n0, (c+2)*GM_KC, t);
            CP_COMMIT();
            CP_WAIT(2);
        } else if (c + 1 < NC) {
            CP_WAIT(1);
        } else {
            CP_WAIT(0);
        }
        __syncthreads();

        uint32_t sbA = sbA0 + cur*A_BUFH2*4;
        uint32_t sbB = sbB0 + cur*B_BUFHH*4 + bln;
        #pragma unroll
        for (int ks = 0; ks < 2; ++ks) {
            int kb = ks*8;
            uint32_t bf[8][2];
            #pragma unroll
            for (int nbp = 0; nbp < 4; ++nbp) {
                uint32_t br[4];
                ldsm4t(br, sbB + ks*16*(SBHH*2) + nbp*32);
                bf[2*nbp][0]   = br[0]; bf[2*nbp][1]   = br[1];
                bf[2*nbp+1][0] = br[2]; bf[2*nbp+1][1] = br[3];
            }
            #pragma unroll
            for (int m = 0; m < 4; ++m) {
                int mr = w*64 + m*16;
                uint32_t af[4];
                ldsm4(af, sbA + ((mr + roff)*SAH + kb + koff)*4);
                #pragma unroll
                for (int n = 0; n < 8; ++n) MMA_F16(acc[m][n], af, bf[n]);
            }
        }
        __syncthreads();
    }

    // epilogue: add fA, write fp16 fpre, accumulate column stats (fp32)
    uint32_t* FPv = (uint32_t*)g_fpreh;
    float sloc[8][2], qloc[8][2];
    #pragma unroll
    for (int n = 0; n < 8; ++n) { sloc[n][0]=0.f; sloc[n][1]=0.f; qloc[n][0]=0.f; qloc[n][1]=0.f; }
    #pragma unroll
    for (int m = 0; m < 4; ++m) {
        size_t rA = row0 + w*64 + m*16 + g;
        size_t rB = rA + 8;
        size_t pA = rA / KNBR, pB = rB / KNBR;
        #pragma unroll
        for (int n = 0; n < 8; ++n) {
            int col = n0 + n*8 + 2*tig;
            float2 fa = *(const float2*)&g_fA[pA*C3 + col];
            float2 fb = *(const float2*)&g_fA[pB*C3 + col];
            float v0 = acc[m][n][0]+fa.x, v1 = acc[m][n][1]+fa.y;
            float v2 = acc[m][n][2]+fb.x, v3 = acc[m][n][3]+fb.y;
            FPv[rA*(C3/2) + col/2] = pack_h2(v0, v1);
            FPv[rB*(C3/2) + col/2] = pack_h2(v2, v3);
            sloc[n][0] += v0 + v2;   qloc[n][0] += v0*v0 + v2*v2;
            sloc[n][1] += v1 + v3;   qloc[n][1] += v1*v1 + v3*v3;
        }
    }
    #pragma unroll
    for (int n = 0; n < 8; ++n)
        #pragma unroll
        for (int j = 0; j < 2; ++j) {
            float s = sloc[n][j], q = qloc[n][j];
            #pragma unroll
            for (int mk = 4; mk <= 16; mk <<= 1) {
                s += __shfl_xor_sync(0xffffffffu, s, mk);
                q += __shfl_xor_sync(0xffffffffu, q, mk);
            }
            if (g == 0) {
                int ci = n*8 + 2*tig + j;
                sstat[(w*64 + ci)*2 + 0] = s;
                sstat[(w*64 + ci)*2 + 1] = q;
            }
        }
    __syncthreads();
    if (t < 128) {
        int ci = t >> 1, which = t & 1;
        float v = sstat[(0*64+ci)*2+which] + sstat[(1*64+ci)*2+which]
                + sstat[(2*64+ci)*2+which] + sstat[(3*64+ci)*2+which];
        g_p3[(size_t)blockIdx.y*(2*C3) + (size_t)which*C3 + n0 + ci] = v;
    }
}

// ---------------------------------------------------------------------------
// fin3: reduce partials, emit fp32 and half2-packed BN params
// ---------------------------------------------------------------------------
__global__ void fin3_kernel(const float* __restrict__ g3,
                            const float* __restrict__ be3) {
    __shared__ float tmp[2*C3];
    int c = threadIdx.x;   // 512
    float s = 0.f, q = 0.f;
    for (int i = 0; i < NROWS/GM_MT2; ++i) {
        s += g_p3[(size_t)i*(2*C3) + c];
        q += g_p3[(size_t)i*(2*C3) + C3 + c];
    }
    float mu  = s / (float)NROWS;
    float var = q / (float)NROWS - mu*mu;
    float sc  = g3[c] * rsqrtf(var + BN_EPS);
    float sh  = be3[c] - mu*sc;
    g_ss3[c]    = sc;
    g_ss3[C3+c] = sh;
    tmp[c] = sc; tmp[C3+c] = sh;
    __syncthreads();
    if (c < C3/2) {
        g_ss3h[c]          = pack_h2(tmp[2*c],      tmp[2*c+1]);
        g_ss3h[C3/2 + c]   = pack_h2(tmp[C3+2*c],   tmp[C3+2*c+1]);
    }
}

// ---------------------------------------------------------------------------
// init keys
// ---------------------------------------------------------------------------
__global__ void initkeys_kernel(unsigned* __restrict__ keys) {
    int i = blockIdx.x*256 + threadIdx.x;
    if (i < NPTS*CH) keys[i] = 0u;
}

// ---------------------------------------------------------------------------
// gemm_final: 3-stage cp.async, CTA 256x64, ldmatrix A + half2 BN at fragment
// load, ldmatrix.trans B, grouped atomicMax maxpool epilogue.
// ---------------------------------------------------------------------------
#define GF_SMEM ((3*A_BUFH2 + 3*B_BUFHH + 512)*4)
__global__ __launch_bounds__(128) void gemm_final_kernel(unsigned* __restrict__ keys) {
    extern __shared__ __align__(16) uint32_t dyn[];
    uint32_t* bufA = dyn;
    __half*  bufB = (__half*)(dyn + 3*A_BUFH2);
    uint32_t* sSh = dyn + 3*A_BUFH2 + 3*B_BUFHH;   // [sc2 256][sh2 256]
    int t = threadIdx.x;
    int w = t >> 5, lane = t & 31;
    int g = lane >> 2, tig = lane & 3;
    int roff = lane & 15, koff = (lane >> 4) * 4;
    int btile = lane >> 3, brw = lane & 7;
    size_t row0 = (size_t)blockIdx.y * GM_MT2;
    int n0 = blockIdx.x * GM_NT;
    uint32_t sbA0 = (uint32_t)__cvta_generic_to_shared(bufA);
    uint32_t sbB0 = (uint32_t)__cvta_generic_to_shared(bufB);
    uint32_t bln = ((btile&1)*8 + brw)*(SBHH*2) + (btile>>1)*16;

    float acc[4][8][4] = {};
    const int NC = C3/GM_KC;  // 16

    for (int i = t; i < 2*(C3/2); i += 128) sSh[i] = g_ss3h[i];

    g4_load(bufA, bufB, row0, n0, 0, t);                        CP_COMMIT();
    g4_load(bufA + A_BUFH2, bufB + 2*B_BUFHH, row0, n0, 32, t); CP_COMMIT();

    for (int c = 0; c < NC; ++c) {
        int cur = c % 3;
        if (c + 2 < NC) {
            int st = (c+2) % 3;
            g4_load(bufA + st*A_BUFH2, bufB + st*2*B_BUFHH, row0, n0, (c+2)*GM_KC, t);
            CP_COMMIT();
            CP_WAIT(2);
        } else if (c + 1 < NC) {
            CP_WAIT(1);
        } else {
            CP_WAIT(0);
        }
        __syncthreads();

        uint32_t sbA = sbA0 + cur*A_BUFH2*4;
        uint32_t sbB = sbB0 + cur*B_BUFHH*4 + bln;
        int kk = c*GM_KC;
        #pragma unroll
        for (int ks = 0; ks < 2; ++ks) {
            int kb = ks*8;
            int kpg0 = (kk>>1) + kb + tig;
            uint32_t sc0 = sSh[kpg0],     sh0 = sSh[C3/2 + kpg0];
            uint32_t sc4 = sSh[kpg0 + 4], sh4 = sSh[C3/2 + kpg0 + 4];
            uint32_t bf[8][2];
            #pragma unroll
            for (int nbp = 0; nbp < 4; ++nbp) {
                uint32_t br[4];
                ldsm4t(br, sbB + ks*16*(SBHH*2) + nbp*32);
                bf[2*nbp][0]   = br[0]; bf[2*nbp][1]   = br[1];
                bf[2*nbp+1][0] = br[2]; bf[2*nbp+1][1] = br[3];
            }
            #pragma unroll
            for (int m = 0; m < 4; ++m) {
                int mr = w*64 + m*16;
                uint32_t af[4];
                ldsm4(af, sbA + ((mr + roff)*SAH + kb + koff)*4);
                af[0] = bnfrag_h2(af[0], sc0, sh0);
                af[1] = bnfrag_h2(af[1], sc0, sh0);
                af[2] = bnfrag_h2(af[2], sc4, sh4);
                af[3] = bnfrag_h2(af[3], sc4, sh4);
                #pragma unroll
                for (int n = 0; n < 8; ++n) MMA_F16(acc[m][n], af, bf[n]);
            }
        }
        __syncthreads();
    }

    // grouped-atomic maxpool epilogue
    #pragma unroll
    for (int n = 0; n < 8; ++n) {
        #pragma unroll
        for (int cc = 0; cc < 2; ++cc) {
            int col = n0 + n*8 + 2*tig + cc;
            size_t curp = (row0 + w*64 + g) / KNBR;
            float rm = -FLT_MAX;
            #pragma unroll
            for (int j = 0; j < 8; ++j) {
                size_t row = row0 + w*64 + g + 8*j;
                size_t pj = row / KNBR;
                float v = acc[j>>1][n][((j&1)<<1) + cc];
                if (pj != curp) {
                    atomicMax(&keys[curp*CH + col], fenc(rm));
                    curp = pj; rm = v;
                } else {
                    rm = fmaxf(rm, v);
                }
            }
            atomicMax(&keys[curp*CH + col], fenc(rm));
        }
    }
}

// ---------------------------------------------------------------------------
// decode keys in place + add b4
// ---------------------------------------------------------------------------
__global__ void decode_kernel(float* __restrict__ out, const float* __restrict__ b4) {
    int i = blockIdx.x*256 + threadIdx.x;
    if (i < NPTS*CH) {
        int c = i % CH;
        unsigned k = ((const unsigned*)(out + (size_t)BB*NN*3))[i];
        out[(size_t)BB*NN*3 + i] = fdec(k) + b4[c];
    }
}

__global__ void copy_xyz_kernel(const float* __restrict__ xyz,
                                float* __restrict__ out) {
    int i = blockIdx.x*256 + threadIdx.x;
    if (i < BB*NN*3) out[i] = xyz[i];
}

extern "C" void kernel_launch(void* const* d_in, const int* in_sizes, int n_in,
                              void* d_out, int out_size) {
    (void)in_sizes; (void)n_in; (void)out_size;
    const float* xyz = (const float*)d_in[0];
    const float* W1  = (const float*)d_in[1];
    const float* b1  = (const float*)d_in[2];
    const float* g1  = (const float*)d_in[3];
    const float* be1 = (const float*)d_in[4];
    const float* W2  = (const float*)d_in[5];
    const float* b2  = (const float*)d_in[6];
    const float* W3  = (const float*)d_in[7];
    const float* b3  = (const float*)d_in[8];
    const float* g3  = (const float*)d_in[9];
    const float* be3 = (const float*)d_in[10];
    const float* W4  = (const float*)d_in[11];
    const float* b4  = (const float*)d_in[12];
    float* out = (float*)d_out;
    unsigned* keys = (unsigned*)(out + (size_t)BB*NN*3);

    static int smem_set = 0;
    if (!smem_set) {
        cudaFuncSetAttribute(gemm3_kernel, cudaFuncAttributeMaxDynamicSharedMemorySize, G3_SMEM);
        cudaFuncSetAttribute(gemm_final_kernel, cudaFuncAttributeMaxDynamicSharedMemorySize, GF_SMEM);
        smem_set = 1;
    }

    knn_kernel<<<NPTS, 256>>>(xyz);
    stats1_kernel<<<STAT_BLOCKS, 128>>>(xyz, W1, b1);
    fin1_kernel<<<1, C1>>>(g1, be1);
    edge_kernel<<<NROWS/16, 256>>>(xyz, W1, b1);
    w3h_kernel<<<(256*C3 + 255)/256, 256>>>(W3);
    w4h_kernel<<<(C3*CH + 255)/256, 256>>>(W4);
    {
        dim3 grid2(C2/GM_NT, NROWS/GM_MT);   // (4, 1280)
        gemm2_kernel<<<grid2, 128>>>(W2, b2);
    }
    gmax_kernel<<<NPTS, 128>>>();
    {
        dim3 gridFA(C3/GM_NT, NPTS/GM_MT);   // (8, 64)
        gemmFA_kernel<<<gridFA, 128>>>(W3, b3);
    }
    {
        dim3 grid3(C3/GM_NT, NROWS/GM_MT2);  // (8, 640)
        gemm3_kernel<<<grid3, 128, G3_SMEM>>>();
    }
    fin3_kernel<<<1, C3>>>(g3, be3);
    initkeys_kernel<<<(NPTS*CH + 255)/256, 256>>>(keys);
    {
        dim3 grid4(CH/GM_NT, NROWS/GM_MT2);  // (6, 640)
        gemm_final_kernel<<<grid4, 128, GF_SMEM>>>(keys);
    }
    decode_kernel<<<(NPTS*CH + 255)/256, 256>>>(out, b4);
    copy_xyz_kernel<<<(BB*NN*3 + 255)/256, 256>>>(xyz, out);
}

// round 14
// speedup vs baseline: 1.0548x; 1.0548x over previous
#include <cuda_runtime.h>
#include <cuda_fp16.h>
#include <math.h>
#include <float.h>
#include <stdint.h>

// Problem constants
#define BB 2
#define NN 4096
#define KNBR 20
#define NPTS (BB*NN)            // 8192
#define NROWS (NPTS*KNBR)       // 163840
#define C1 128
#define C2 256
#define C3 512
#define CH 384
#define BN_EPS 1e-5f
#define STAT_BLOCKS 1024
#define ROWS_PER_STAT (NROWS/STAT_BLOCKS) // 160

__device__ __forceinline__ void cp16(void* dst, const void* src) {
    uint32_t s = (uint32_t)__cvta_generic_to_shared(dst);
    asm volatile("cp.async.cg.shared.global [%0], [%1], 16;" :: "r"(s), "l"(src));
}
#define CP_COMMIT() asm volatile("cp.async.commit_group;" ::: "memory")
#define CP_WAIT(n)  asm volatile("cp.async.wait_group %0;" :: "n"(n) : "memory")

__device__ __forceinline__ uint32_t pack_h2(float a, float b) {
    __half2 h = __floats2half2_rn(a, b);
    return *(uint32_t*)&h;
}

// ldmatrix x4 (A fragments)
__device__ __forceinline__ void ldsm4(uint32_t* r, uint32_t saddr) {
    asm volatile("ldmatrix.sync.aligned.m8n8.x4.shared.b16 {%0,%1,%2,%3}, [%4];"
        : "=r"(r[0]), "=r"(r[1]), "=r"(r[2]), "=r"(r[3]) : "r"(saddr));
}

// order-preserving float<->uint for atomicMax
__device__ __forceinline__ unsigned fenc(float f) {
    int b = __float_as_int(f);
    return (b < 0) ? ~((unsigned)b) : (((unsigned)b) | 0x80000000u);
}
__device__ __forceinline__ float fdec(unsigned k) {
    return (k & 0x80000000u) ? __int_as_float((int)(k ^ 0x80000000u))
                             : __int_as_float((int)(~k));
}

// bn3+relu on an fp16x2 fragment in half2 math (HFMA2 + HMAX2)
__device__ __forceinline__ uint32_t bnfrag_h2(uint32_t a, uint32_t sc2, uint32_t sh2) {
    __half2 r = __hfma2(*(__half2*)&a, *(__half2*)&sc2, *(__half2*)&sh2);
    r = __hmax2(r, __float2half2_rn(0.f));
    return *(uint32_t*)&r;
}

// ---------------- scratch (static device globals) ----------------
__device__ int      g_idx[NROWS];
__device__ float    g_part1[STAT_BLOCKS*2*C1];
__device__ float    g_ss1[2*C1];
__device__ __half   g_Ah[(size_t)NROWS*C1];      // 42 MB
__device__ __half   g_H2h[(size_t)NROWS*C2];     // 84 MB
__device__ __half   g_gmaxh[(size_t)NPTS*C2];
__device__ float    g_fA[(size_t)NPTS*C3];
__device__ __half   g_fpreh[(size_t)NROWS*C3];   // 168 MB
__device__ float    g_p3[(size_t)(NROWS/128)*2*C3];
__device__ float    g_ss3[2*C3];
__device__ uint32_t g_ss3h[2*(C3/2)];            // half2-packed: [sc 256][sh 256]
__device__ uint32_t g_w3h[128*C3];               // W3[256:512] packed [k/2][col]
__device__ uint32_t g_w4h[256*CH];               // W4 packed [k/2][col]

// ---------------------------------------------------------------------------
// K1: KNN (unchanged — passing, R9)
// ---------------------------------------------------------------------------
__global__ void knn_kernel(const float* __restrict__ xyz) {
    __shared__ float sd[NN];
    __shared__ float rv[8];
    __shared__ int   ri8[8];
    __shared__ int   swin;
    int p = blockIdx.x;
    int b = p >> 12, n = p & (NN-1);
    int t = threadIdx.x, lane = t & 31, w = t >> 5;
    const float* base = xyz + (size_t)b*NN*3;
    float cx = base[n*3+0], cy = base[n*3+1], cz = base[n*3+2];
    float pp = cx*cx + cy*cy + cz*cz;
    float bv = FLT_MAX; int bi = NN;
    for (int m = t; m < NN; m += 256) {
        float qx = base[m*3+0], qy = base[m*3+1], qz = base[m*3+2];
        float d2 = pp + (qx*qx + qy*qy + qz*qz) - 2.f*(cx*qx + cy*qy + cz*qz);
        sd[m] = d2;
        if (d2 < bv) { bv = d2; bi = m; }
    }
    __syncthreads();
    for (int round = 0; round < KNBR; ++round) {
        float rb = bv; int rx = bi;
        #pragma unroll
        for (int off = 16; off > 0; off >>= 1) {
            float ov = __shfl_down_sync(0xffffffffu, rb, off);
            int   oi = __shfl_down_sync(0xffffffffu, rx, off);
            if (ov < rb || (ov == rb && oi < rx)) { rb = ov; rx = oi; }
        }
        if (lane == 0) { rv[w] = rb; ri8[w] = rx; }
        __syncthreads();
        if (w == 0) {
            float v2 = (lane < 8) ? rv[lane] : FLT_MAX;
            int   i2 = (lane < 8) ? ri8[lane] : NN;
            #pragma unroll
            for (int off = 4; off > 0; off >>= 1) {
                float ov = __shfl_down_sync(0xffffffffu, v2, off);
                int   oi = __shfl_down_sync(0xffffffffu, i2, off);
                if (ov < v2 || (ov == v2 && oi < i2)) { v2 = ov; i2 = oi; }
            }
            if (lane == 0) {
                g_idx[p*KNBR + round] = i2;
                sd[i2] = FLT_MAX;
                swin = i2;
            }
        }
        __syncthreads();
        if (bi == swin) {
            bv = FLT_MAX; bi = NN;
            for (int m = t; m < NN; m += 256) {
                float v = sd[m];
                if (v < bv) { bv = v; bi = m; }
            }
        }
    }
}

// ---------------------------------------------------------------------------
// BN1 stats (unchanged)
// ---------------------------------------------------------------------------
__global__ void stats1_kernel(const float* __restrict__ xyz,
                              const float* __restrict__ W1,
                              const float* __restrict__ b1) {
    __shared__ float se[ROWS_PER_STAT*6];
    int blk = blockIdx.x, t = threadIdx.x;
    int row0 = blk * ROWS_PER_STAT;
    for (int r = t; r < ROWS_PER_STAT; r += 128) {
        int gr = row0 + r;
        int p  = gr / KNBR;
        int b  = p >> 12, n = p & (NN-1);
        int id = g_idx[gr];
        const float* cb = xyz + ((size_t)b*NN + n)*3;
        const float* nb = xyz + ((size_t)b*NN + id)*3;
        se[r*6+0] = nb[0]-cb[0];
        se[r*6+1] = nb[1]-cb[1];
        se[r*6+2] = nb[2]-cb[2];
        se[r*6+3] = cb[0]; se[r*6+4] = cb[1]; se[r*6+5] = cb[2];
    }
    __syncthreads();
    float w0 = W1[0*C1+t], w1 = W1[1*C1+t], w2 = W1[2*C1+t],
          w3 = W1[3*C1+t], w4 = W1[4*C1+t], w5 = W1[5*C1+t], bb = b1[t];
    float s = 0.f, q = 0.f;
    for (int r = 0; r < ROWS_PER_STAT; ++r) {
        float h = bb + se[r*6+0]*w0 + se[r*6+1]*w1 + se[r*6+2]*w2
                     + se[r*6+3]*w3 + se[r*6+4]*w4 + se[r*6+5]*w5;
        s += h; q += h*h;
    }
    g_part1[blk*(2*C1) + t]      = s;
    g_part1[blk*(2*C1) + C1 + t] = q;
}

__global__ void fin1_kernel(const float* __restrict__ g1,
                            const float* __restrict__ be1) {
    int c = threadIdx.x;
    float s = 0.f, q = 0.f;
    for (int i = 0; i < STAT_BLOCKS; ++i) {
        s += g_part1[i*(2*C1)+c];
        q += g_part1[i*(2*C1)+C1+c];
    }
    float mu  = s / (float)NROWS;
    float var = q / (float)NROWS - mu*mu;
    float sc  = g1[c] * rsqrtf(var + BN_EPS);
    g_ss1[c]     = sc;
    g_ss1[C1+c]  = be1[c] - mu*sc;
}

// ---------------------------------------------------------------------------
// edge16: writes fp16 A (unchanged)
// ---------------------------------------------------------------------------
__global__ __launch_bounds__(256) void edge_kernel(
    const float* __restrict__ xyz,
    const float* __restrict__ W1, const float* __restrict__ b1) {
    __shared__ float sE[16*6];
    int row0 = blockIdx.x * 16, t = threadIdx.x;
    if (t < 96) {
        int r = t / 6, d = t - r*6;
        int row = row0 + r;
        int p = row / KNBR;
        int b = p >> 12, n = p & (NN-1);
        float v;
        if (d < 3) {
            int id = g_idx[row];
            v = xyz[((size_t)b*NN + id)*3 + d] - xyz[((size_t)b*NN + n)*3 + d];
        } else {
            v = xyz[((size_t)b*NN + n)*3 + (d-3)];
        }
        sE[r*6 + d] = v;
    }
    __syncthreads();
    int c = t & (C1-1), h = t >> 7;
    float w0 = W1[0*C1+c], w1 = W1[1*C1+c], w2 = W1[2*C1+c],
          w3 = W1[3*C1+c], w4 = W1[4*C1+c], w5 = W1[5*C1+c];
    float bb = b1[c], sc = g_ss1[c], sh = g_ss1[C1+c];
    #pragma unroll
    for (int rr = 0; rr < 8; ++rr) {
        int r = h*8 + rr;
        float hv = bb + sE[r*6+0]*w0 + sE[r*6+1]*w1 + sE[r*6+2]*w2
                      + sE[r*6+3]*w3 + sE[r*6+4]*w4 + sE[r*6+5]*w5;
        hv = fmaxf(hv*sc + sh, 0.f);
        g_Ah[(size_t)(row0 + r)*C1 + c] = __float2half_rn(hv);
    }
}

// ---------------------------------------------------------------------------
// weight prep: half2-packed [k/2][col] (R12 layout)
// ---------------------------------------------------------------------------
__global__ void w3h_kernel(const float* __restrict__ W3) {
    int i = blockIdx.x*256 + threadIdx.x;
    if (i < 128*C3) {
        int kp = i / C3, col = i - kp*C3;
        g_w3h[i] = pack_h2(W3[(size_t)(C2 + 2*kp)*C3 + col],
                           W3[(size_t)(C2 + 2*kp + 1)*C3 + col]);
    }
}
__global__ void w4h_kernel(const float* __restrict__ W4) {
    int i = blockIdx.x*256 + threadIdx.x;
    if (i < 256*CH) {
        int kp = i / CH, col = i - kp*CH;
        g_w4h[i] = pack_h2(W4[(size_t)(2*kp)*CH + col],
                           W4[(size_t)(2*kp + 1)*CH + col]);
    }
}

// ===========================================================================
// fp16 m16n8k16 tile configs
// ===========================================================================
#define GM_MT 128
#define GM_MT2 256
#define GM_NT 64
#define GM_KC 32
#define SAH 20
#define SBH 72
#define A_BUFH  (GM_MT*SAH)     // 2560 u32
#define A_BUFH2 (GM_MT2*SAH)    // 5120 u32
#define B_BUFH  (16*SBH)        // 1152 u32

#define MMA_F16(acc, af, bf) \
    asm volatile( \
        "mma.sync.aligned.m16n8k16.row.col.f32.f16.f16.f32 " \
        "{%0,%1,%2,%3}, {%4,%5,%6,%7}, {%8,%9}, {%0,%1,%2,%3};" \
        : "+f"((acc)[0]), "+f"((acc)[1]), "+f"((acc)[2]), "+f"((acc)[3]) \
        : "r"((af)[0]), "r"((af)[1]), "r"((af)[2]), "r"((af)[3]), \
          "r"((bf)[0]), "r"((bf)[1]))

// ---------------------------------------------------------------------------
// gemm2: H2 = A @ W2 + b2 (fp16 in, fp16 out). CTA 128x64. (unchanged)
// ---------------------------------------------------------------------------
__global__ __launch_bounds__(128) void gemm2_kernel(
    const float* __restrict__ W2, const float* __restrict__ b2) {
    __shared__ __align__(16) uint32_t sA[GM_MT*SAH];
    __shared__ __align__(16) uint32_t sB[16*SBH];
    int t = threadIdx.x;
    int w = t >> 5, lane = t & 31;
    int g = lane >> 2, tig = lane & 3;
    size_t row0 = (size_t)blockIdx.y * GM_MT;
    int n0 = blockIdx.x * GM_NT;

    float acc[2][8][4] = {};

    for (int kk = 0; kk < C1; kk += GM_KC) {
        #pragma unroll
        for (int pq = 0; pq < 4; ++pq) {
            int r = pq*32 + (t>>2), seg = t&3;
            uint4 v = *(const uint4*)(g_Ah + (row0 + r)*C1 + kk + seg*8);
            *(uint4*)&sA[r*SAH + seg*4] = v;
        }
        #pragma unroll
        for (int pq = 0; pq < 2; ++pq) {
            int kp = pq*8 + (t>>4), colb = (t&15)*4;
            const float* s0 = &W2[(size_t)(kk + 2*kp)*C2 + n0 + colb];
            float4 va = *(const float4*)s0;
            float4 vb = *(const float4*)(s0 + C2);
            uint4 o = make_uint4(pack_h2(va.x, vb.x), pack_h2(va.y, vb.y),
                                 pack_h2(va.z, vb.z), pack_h2(va.w, vb.w));
            *(uint4*)&sB[kp*SBH + colb] = o;
        }
        __syncthreads();
        #pragma unroll
        for (int ks = 0; ks < 2; ++ks) {
            int kb = ks*8;
            uint32_t bf[8][2];
            #pragma unroll
            for (int n = 0; n < 8; ++n) {
                bf[n][0] = sB[(kb+tig)*SBH   + n*8 + g];
                bf[n][1] = sB[(kb+tig+4)*SBH + n*8 + g];
            }
            #pragma unroll
            for (int m = 0; m < 2; ++m) {
                int mr = w*32 + m*16;
                uint32_t af[4];
                af[0] = sA[(mr+g)*SAH   + kb + tig];
                af[1] = sA[(mr+g+8)*SAH + kb + tig];
                af[2] = sA[(mr+g)*SAH   + kb + tig + 4];
                af[3] = sA[(mr+g+8)*SAH + kb + tig + 4];
                #pragma unroll
                for (int n = 0; n < 8; ++n) MMA_F16(acc[m][n], af, bf[n]);
            }
        }
        __syncthreads();
    }
    uint32_t* H2v = (uint32_t*)g_H2h;
    #pragma unroll
    for (int m = 0; m < 2; ++m) {
        size_t r0 = row0 + w*32 + m*16 + g;
        #pragma unroll
        for (int n = 0; n < 8; ++n) {
            int col = n0 + n*8 + 2*tig;
            float2 bb = *(const float2*)&b2[col];
            H2v[r0*(C2/2) + col/2]     = pack_h2(acc[m][n][0]+bb.x, acc[m][n][1]+bb.y);
            H2v[(r0+8)*(C2/2) + col/2] = pack_h2(acc[m][n][2]+bb.x, acc[m][n][3]+bb.y);
        }
    }
}

// ---------------------------------------------------------------------------
// gmax over fp16 pairs (unchanged)
// ---------------------------------------------------------------------------
__global__ void gmax_kernel() {
    int p = blockIdx.x, t = threadIdx.x;   // 128 threads
    const __half2* src = (const __half2*)g_H2h + (size_t)p*KNBR*(C2/2) + t;
    __half2 m = src[0];
    #pragma unroll
    for (int r = 1; r < KNBR; ++r) m = __hmax2(m, src[(size_t)r*(C2/2)]);
    ((__half2*)g_gmaxh)[(size_t)p*(C2/2) + t] = m;
}

// ---------------------------------------------------------------------------
// gemmFA: fA = gmax @ W3[0:256] + b3 (unchanged)
// ---------------------------------------------------------------------------
__global__ __launch_bounds__(128) void gemmFA_kernel(
    const float* __restrict__ W3, const float* __restrict__ b3) {
    __shared__ __align__(16) uint32_t sA[GM_MT*SAH];
    __shared__ __align__(16) uint32_t sB[16*SBH];
    int t = threadIdx.x;
    int w = t >> 5, lane = t & 31;
    int g = lane >> 2, tig = lane & 3;
    size_t row0 = (size_t)blockIdx.y * GM_MT;
    int n0 = blockIdx.x * GM_NT;

    float acc[2][8][4] = {};

    for (int kk = 0; kk < C2; kk += GM_KC) {
        #pragma unroll
        for (int pq = 0; pq < 4; ++pq) {
            int r = pq*32 + (t>>2), seg = t&3;
            uint4 v = *(const uint4*)(g_gmaxh + (row0 + r)*C2 + kk + seg*8);
            *(uint4*)&sA[r*SAH + seg*4] = v;
        }
        #pragma unroll
        for (int pq = 0; pq < 2; ++pq) {
            int kp = pq*8 + (t>>4), colb = (t&15)*4;
            const float* s0 = &W3[(size_t)(kk + 2*kp)*C3 + n0 + colb];
            float4 va = *(const float4*)s0;
            float4 vb = *(const float4*)(s0 + C3);
            uint4 o = make_uint4(pack_h2(va.x, vb.x), pack_h2(va.y, vb.y),
                                 pack_h2(va.z, vb.z), pack_h2(va.w, vb.w));
            *(uint4*)&sB[kp*SBH + colb] = o;
        }
        __syncthreads();
        #pragma unroll
        for (int ks = 0; ks < 2; ++ks) {
            int kb = ks*8;
            uint32_t bf[8][2];
            #pragma unroll
            for (int n = 0; n < 8; ++n) {
                bf[n][0] = sB[(kb+tig)*SBH   + n*8 + g];
                bf[n][1] = sB[(kb+tig+4)*SBH + n*8 + g];
            }
            #pragma unroll
            for (int m = 0; m < 2; ++m) {
                int mr = w*32 + m*16;
                uint32_t af[4];
                af[0] = sA[(mr+g)*SAH   + kb + tig];
                af[1] = sA[(mr+g+8)*SAH + kb + tig];
                af[2] = sA[(mr+g)*SAH   + kb + tig + 4];
                af[3] = sA[(mr+g+8)*SAH + kb + tig + 4];
                #pragma unroll
                for (int n = 0; n < 8; ++n) MMA_F16(acc[m][n], af, bf[n]);
            }
        }
        __syncthreads();
    }
    #pragma unroll
    for (int m = 0; m < 2; ++m) {
        size_t r0 = row0 + w*32 + m*16 + g;
        #pragma unroll
        for (int n = 0; n < 8; ++n) {
            int col = n0 + n*8 + 2*tig;
            float2 bb = *(const float2*)&b3[col];
            *(float2*)&g_fA[r0*C3 + col]     = make_float2(acc[m][n][0]+bb.x, acc[m][n][1]+bb.y);
            *(float2*)&g_fA[(r0+8)*C3 + col] = make_float2(acc[m][n][2]+bb.x, acc[m][n][3]+bb.y);
        }
    }
}

// ---------------------------------------------------------------------------
// big-GEMM load helpers (256 threads)
// ---------------------------------------------------------------------------
__device__ __forceinline__ void g3_load(uint32_t* A, uint32_t* B,
                                        size_t row0, int n0, int kk, int t) {
    #pragma unroll
    for (int pq = 0; pq < 4; ++pq) {
        int r = pq*64 + (t>>2), seg = t&3;
        cp16(&A[r*SAH + seg*4], g_H2h + (row0 + r)*C2 + kk + seg*8);
    }
    int kp = t>>4, s = t&15;
    int kpg = (kk>>1) + kp;
    cp16(&B[kp*SBH + s*4], &g_w3h[(size_t)kpg*C3 + n0 + s*4]);
}
__device__ __forceinline__ void g4_load(uint32_t* A, uint32_t* B,
                                        size_t row0, int n0, int kk, int t) {
    #pragma unroll
    for (int pq = 0; pq < 4; ++pq) {
        int r = pq*64 + (t>>2), seg = t&3;
        cp16(&A[r*SAH + seg*4], g_fpreh + (row0 + r)*C3 + kk + seg*8);
    }
    int kp = t>>4, s = t&15;
    int kpg = (kk>>1) + kp;
    cp16(&B[kp*SBH + s*4], &g_w4h[(size_t)kpg*CH + n0 + s*4]);
}

// ---------------------------------------------------------------------------
// gemm3: 3-stage cp.async, CTA 256x64 with 256 threads (8 warps, warp 32x64),
// ldmatrix A, fused BN3-stat partials.
// ---------------------------------------------------------------------------
#define G3_SMEM ((3*A_BUFH2 + 3*B_BUFH + 1024)*4)
__global__ __launch_bounds__(256) void gemm3_kernel() {
    extern __shared__ __align__(16) uint32_t dyn[];
    uint32_t* bufA = dyn;                          // 3 x A_BUFH2
    uint32_t* bufB = dyn + 3*A_BUFH2;              // 3 x B_BUFH
    float* sstat = (float*)(dyn + 3*A_BUFH2 + 3*B_BUFH);   // [8][64][2]
    int t = threadIdx.x;
    int w = t >> 5, lane = t & 31;
    int g = lane >> 2, tig = lane & 3;
    int roff = lane & 15, koff = (lane >> 4) * 4;
    size_t row0 = (size_t)blockIdx.y * GM_MT2;
    int n0 = blockIdx.x * GM_NT;
    uint32_t sbA0 = (uint32_t)__cvta_generic_to_shared(bufA);

    float acc[2][8][4] = {};
    const int NC = C2/GM_KC;  // 8

    g3_load(bufA, bufB, row0, n0, 0, t);                      CP_COMMIT();
    g3_load(bufA + A_BUFH2, bufB + B_BUFH, row0, n0, 32, t);  CP_COMMIT();

    for (int c = 0; c < NC; ++c) {
        int cur = c % 3;
        if (c + 2 < NC) {
            int st = (c+2) % 3;
            g3_load(bufA + st*A_BUFH2, bufB + st*B_BUFH, row0, n0, (c+2)*GM_KC, t);
            CP_COMMIT();
            CP_WAIT(2);
        } else if (c + 1 < NC) {
            CP_WAIT(1);
        } else {
            CP_WAIT(0);
        }
        __syncthreads();

        uint32_t sbA = sbA0 + cur*A_BUFH2*4;
        uint32_t* B = bufB + cur*B_BUFH;
        #pragma unroll
        for (int ks = 0; ks < 2; ++ks) {
            int kb = ks*8;
            uint32_t bf[8][2];
            #pragma unroll
            for (int n = 0; n < 8; ++n) {
                bf[n][0] = B[(kb+tig)*SBH   + n*8 + g];
                bf[n][1] = B[(kb+tig+4)*SBH + n*8 + g];
            }
            #pragma unroll
            for (int m = 0; m < 2; ++m) {
                int mr = w*32 + m*16;
                uint32_t af[4];
                ldsm4(af, sbA + ((mr + roff)*SAH + kb + koff)*4);
                #pragma unroll
                for (int n = 0; n < 8; ++n) MMA_F16(acc[m][n], af, bf[n]);
            }
        }
        __syncthreads();
    }

    // epilogue: add fA, write fp16 fpre, accumulate column stats (fp32)
    uint32_t* FPv = (uint32_t*)g_fpreh;
    float sloc[8][2], qloc[8][2];
    #pragma unroll
    for (int n = 0; n < 8; ++n) { sloc[n][0]=0.f; sloc[n][1]=0.f; qloc[n][0]=0.f; qloc[n][1]=0.f; }
    #pragma unroll
    for (int m = 0; m < 2; ++m) {
        size_t rA = row0 + w*32 + m*16 + g;
        size_t rB = rA + 8;
        size_t pA = rA / KNBR, pB = rB / KNBR;
        #pragma unroll
        for (int n = 0; n < 8; ++n) {
            int col = n0 + n*8 + 2*tig;
            float2 fa = *(const float2*)&g_fA[pA*C3 + col];
            float2 fb = *(const float2*)&g_fA[pB*C3 + col];
            float v0 = acc[m][n][0]+fa.x, v1 = acc[m][n][1]+fa.y;
            float v2 = acc[m][n][2]+fb.x, v3 = acc[m][n][3]+fb.y;
            FPv[rA*(C3/2) + col/2] = pack_h2(v0, v1);
            FPv[rB*(C3/2) + col/2] = pack_h2(v2, v3);
            sloc[n][0] += v0 + v2;   qloc[n][0] += v0*v0 + v2*v2;
            sloc[n][1] += v1 + v3;   qloc[n][1] += v1*v1 + v3*v3;
        }
    }
    #pragma unroll
    for (int n = 0; n < 8; ++n)
        #pragma unroll
        for (int j = 0; j < 2; ++j) {
            float s = sloc[n][j], q = qloc[n][j];
            #pragma unroll
            for (int mk = 4; mk <= 16; mk <<= 1) {
                s += __shfl_xor_sync(0xffffffffu, s, mk);
                q += __shfl_xor_sync(0xffffffffu, q, mk);
            }
            if (g == 0) {
                int ci = n*8 + 2*tig + j;
                sstat[(w*64 + ci)*2 + 0] = s;
                sstat[(w*64 + ci)*2 + 1] = q;
            }
        }
    __syncthreads();
    if (t < 128) {
        int ci = t >> 1, which = t & 1;
        float v = 0.f;
        #pragma unroll
        for (int ww = 0; ww < 8; ++ww) v += sstat[(ww*64+ci)*2+which];
        g_p3[(size_t)blockIdx.y*(2*C3) + (size_t)which*C3 + n0 + ci] = v;
    }
}

// ---------------------------------------------------------------------------
// fin3: reduce partials, emit fp32 and half2-packed BN params
// ---------------------------------------------------------------------------
__global__ void fin3_kernel(const float* __restrict__ g3,
                            const float* __restrict__ be3) {
    __shared__ float tmp[2*C3];
    int c = threadIdx.x;   // 512
    float s = 0.f, q = 0.f;
    for (int i = 0; i < NROWS/GM_MT2; ++i) {
        s += g_p3[(size_t)i*(2*C3) + c];
        q += g_p3[(size_t)i*(2*C3) + C3 + c];
    }
    float mu  = s / (float)NROWS;
    float var = q / (float)NROWS - mu*mu;
    float sc  = g3[c] * rsqrtf(var + BN_EPS);
    float sh  = be3[c] - mu*sc;
    g_ss3[c]    = sc;
    g_ss3[C3+c] = sh;
    tmp[c] = sc; tmp[C3+c] = sh;
    __syncthreads();
    if (c < C3/2) {
        g_ss3h[c]          = pack_h2(tmp[2*c],      tmp[2*c+1]);
        g_ss3h[C3/2 + c]   = pack_h2(tmp[C3+2*c],   tmp[C3+2*c+1]);
    }
}

// ---------------------------------------------------------------------------
// init keys
// ---------------------------------------------------------------------------
__global__ void initkeys_kernel(unsigned* __restrict__ keys) {
    int i = blockIdx.x*256 + threadIdx.x;
    if (i < NPTS*CH) keys[i] = 0u;
}

// ---------------------------------------------------------------------------
// gemm_final: 3-stage cp.async, CTA 256x64 with 256 threads (8 warps),
// ldmatrix A + half2 BN at fragment load, grouped atomicMax maxpool epilogue.
// ---------------------------------------------------------------------------
#define GF_SMEM ((3*A_BUFH2 + 3*B_BUFH + 512)*4)
__global__ __launch_bounds__(256) void gemm_final_kernel(unsigned* __restrict__ keys) {
    extern __shared__ __align__(16) uint32_t dyn[];
    uint32_t* bufA = dyn;
    uint32_t* bufB = dyn + 3*A_BUFH2;
    uint32_t* sSh = dyn + 3*A_BUFH2 + 3*B_BUFH;   // [sc2 256][sh2 256]
    int t = threadIdx.x;
    int w = t >> 5, lane = t & 31;
    int g = lane >> 2, tig = lane & 3;
    int roff = lane & 15, koff = (lane >> 4) * 4;
    size_t row0 = (size_t)blockIdx.y * GM_MT2;
    int n0 = blockIdx.x * GM_NT;
    uint32_t sbA0 = (uint32_t)__cvta_generic_to_shared(bufA);

    float acc[2][8][4] = {};
    const int NC = C3/GM_KC;  // 16

    for (int i = t; i < 2*(C3/2); i += 256) sSh[i] = g_ss3h[i];

    g4_load(bufA, bufB, row0, n0, 0, t);                      CP_COMMIT();
    g4_load(bufA + A_BUFH2, bufB + B_BUFH, row0, n0, 32, t);  CP_COMMIT();

    for (int c = 0; c < NC; ++c) {
        int cur = c % 3;
        if (c + 2 < NC) {
            int st = (c+2) % 3;
            g4_load(bufA + st*A_BUFH2, bufB + st*B_BUFH, row0, n0, (c+2)*GM_KC, t);
            CP_COMMIT();
            CP_WAIT(2);
        } else if (c + 1 < NC) {
            CP_WAIT(1);
        } else {
            CP_WAIT(0);
        }
        __syncthreads();

        uint32_t sbA = sbA0 + cur*A_BUFH2*4;
        uint32_t* B = bufB + cur*B_BUFH;
        int kk = c*GM_KC;
        #pragma unroll
        for (int ks = 0; ks < 2; ++ks) {
            int kb = ks*8;
            int kpg0 = (kk>>1) + kb + tig;
            uint32_t sc0 = sSh[kpg0],     sh0 = sSh[C3/2 + kpg0];
            uint32_t sc4 = sSh[kpg0 + 4], sh4 = sSh[C3/2 + kpg0 + 4];
            uint32_t bf[8][2];
            #pragma unroll
            for (int n = 0; n < 8; ++n) {
                bf[n][0] = B[(kb+tig)*SBH   + n*8 + g];
                bf[n][1] = B[(kb+tig+4)*SBH + n*8 + g];
            }
            #pragma unroll
            for (int m = 0; m < 2; ++m) {
                int mr = w*32 + m*16;
                uint32_t af[4];
                ldsm4(af, sbA + ((mr + roff)*SAH + kb + koff)*4);
                af[0] = bnfrag_h2(af[0], sc0, sh0);
                af[1] = bnfrag_h2(af[1], sc0, sh0);
                af[2] = bnfrag_h2(af[2], sc4, sh4);
                af[3] = bnfrag_h2(af[3], sc4, sh4);
                #pragma unroll
                for (int n = 0; n < 8; ++n) MMA_F16(acc[m][n], af, bf[n]);
            }
        }
        __syncthreads();
    }

    // grouped-atomic maxpool epilogue: thread's 4 rows per col are
    // row0+w*32+g+8j (j=0..3); run-length combine by point before atomicMax.
    #pragma unroll
    for (int n = 0; n < 8; ++n) {
        #pragma unroll
        for (int cc = 0; cc < 2; ++cc) {
            int col = n0 + n*8 + 2*tig + cc;
            size_t curp = (row0 + w*32 + g) / KNBR;
            float rm = -FLT_MAX;
            #pragma unroll
            for (int j = 0; j < 4; ++j) {
                size_t row = row0 + w*32 + g + 8*j;
                size_t pj = row / KNBR;
                float v = acc[j>>1][n][((j&1)<<1) + cc];
                if (pj != curp) {
                    atomicMax(&keys[curp*CH + col], fenc(rm));
                    curp = pj; rm = v;
                } else {
                    rm = fmaxf(rm, v);
                }
            }
            atomicMax(&keys[curp*CH + col], fenc(rm));
        }
    }
}

// ---------------------------------------------------------------------------
// decode keys in place + add b4
// ---------------------------------------------------------------------------
__global__ void decode_kernel(float* __restrict__ out, const float* __restrict__ b4) {
    int i = blockIdx.x*256 + threadIdx.x;
    if (i < NPTS*CH) {
        int c = i % CH;
        unsigned k = ((const unsigned*)(out + (size_t)BB*NN*3))[i];
        out[(size_t)BB*NN*3 + i] = fdec(k) + b4[c];
    }
}

__global__ void copy_xyz_kernel(const float* __restrict__ xyz,
                                float* __restrict__ out) {
    int i = blockIdx.x*256 + threadIdx.x;
    if (i < BB*NN*3) out[i] = xyz[i];
}

extern "C" void kernel_launch(void* const* d_in, const int* in_sizes, int n_in,
                              void* d_out, int out_size) {
    (void)in_sizes; (void)n_in; (void)out_size;
    const float* xyz = (const float*)d_in[0];
    const float* W1  = (const float*)d_in[1];
    const float* b1  = (const float*)d_in[2];
    const float* g1  = (const float*)d_in[3];
    const float* be1 = (const float*)d_in[4];
    const float* W2  = (const float*)d_in[5];
    const float* b2  = (const float*)d_in[6];
    const float* W3  = (const float*)d_in[7];
    const float* b3  = (const float*)d_in[8];
    const float* g3  = (const float*)d_in[9];
    const float* be3 = (const float*)d_in[10];
    const float* W4  = (const float*)d_in[11];
    const float* b4  = (const float*)d_in[12];
    float* out = (float*)d_out;
    unsigned* keys = (unsigned*)(out + (size_t)BB*NN*3);

    static int smem_set = 0;
    if (!smem_set) {
        cudaFuncSetAttribute(gemm3_kernel, cudaFuncAttributeMaxDynamicSharedMemorySize, G3_SMEM);
        cudaFuncSetAttribute(gemm_final_kernel, cudaFuncAttributeMaxDynamicSharedMemorySize, GF_SMEM);
        smem_set = 1;
    }

    knn_kernel<<<NPTS, 256>>>(xyz);
    stats1_kernel<<<STAT_BLOCKS, 128>>>(xyz, W1, b1);
    fin1_kernel<<<1, C1>>>(g1, be1);
    edge_kernel<<<NROWS/16, 256>>>(xyz, W1, b1);
    w3h_kernel<<<(128*C3 + 255)/256, 256>>>(W3);
    w4h_kernel<<<(256*CH + 255)/256, 256>>>(W4);
    {
        dim3 grid2(C2/GM_NT, NROWS/GM_MT);   // (4, 1280)
        gemm2_kernel<<<grid2, 128>>>(W2, b2);
    }
    gmax_kernel<<<NPTS, 128>>>();
    {
        dim3 gridFA(C3/GM_NT, NPTS/GM_MT);   // (8, 64)
        gemmFA_kernel<<<gridFA, 128>>>(W3, b3);
    }
    {
        dim3 grid3(C3/GM_NT, NROWS/GM_MT2);  // (8, 640)
        gemm3_kernel<<<grid3, 256, G3_SMEM>>>();
    }
    fin3_kernel<<<1, C3>>>(g3, be3);
    initkeys_kernel<<<(NPTS*CH + 255)/256, 256>>>(keys);
    {
        dim3 grid4(CH/GM_NT, NROWS/GM_MT2);  // (6, 640)
        gemm_final_kernel<<<grid4, 256, GF_SMEM>>>(keys);
    }
    decode_kernel<<<(NPTS*CH + 255)/256, 256>>>(out, b4);
    copy_xyz_kernel<<<(BB*NN*3 + 255)/256, 256>>>(xyz, out);
}

// round 15
// speedup vs baseline: 1.0699x; 1.0143x over previous
#include <cuda_runtime.h>
#include <cuda_fp16.h>
#include <math.h>
#include <float.h>
#include <stdint.h>

// Problem constants
#define BB 2
#define NN 4096
#define KNBR 20
#define NPTS (BB*NN)            // 8192
#define NROWS (NPTS*KNBR)       // 163840
#define C1 128
#define C2 256
#define C3 512
#define CH 384
#define BN_EPS 1e-5f
#define STAT_BLOCKS 1024
#define ROWS_PER_STAT (NROWS/STAT_BLOCKS) // 160

__device__ __forceinline__ void cp16(void* dst, const void* src) {
    uint32_t s = (uint32_t)__cvta_generic_to_shared(dst);
    asm volatile("cp.async.cg.shared.global [%0], [%1], 16;" :: "r"(s), "l"(src));
}
#define CP_COMMIT() asm volatile("cp.async.commit_group;" ::: "memory")
#define CP_WAIT(n)  asm volatile("cp.async.wait_group %0;" :: "n"(n) : "memory")

__device__ __forceinline__ uint32_t pack_h2(float a, float b) {
    __half2 h = __floats2half2_rn(a, b);
    return *(uint32_t*)&h;
}

// ldmatrix x4 (A fragments)
__device__ __forceinline__ void ldsm4(uint32_t* r, uint32_t saddr) {
    asm volatile("ldmatrix.sync.aligned.m8n8.x4.shared.b16 {%0,%1,%2,%3}, [%4];"
        : "=r"(r[0]), "=r"(r[1]), "=r"(r[2]), "=r"(r[3]) : "r"(saddr));
}

// order-preserving float<->uint for atomicMax
__device__ __forceinline__ unsigned fenc(float f) {
    int b = __float_as_int(f);
    return (b < 0) ? ~((unsigned)b) : (((unsigned)b) | 0x80000000u);
}
__device__ __forceinline__ float fdec(unsigned k) {
    return (k & 0x80000000u) ? __int_as_float((int)(k ^ 0x80000000u))
                             : __int_as_float((int)(~k));
}

// bn3+relu on an fp16x2 fragment in half2 math (HFMA2 + HMAX2)
__device__ __forceinline__ uint32_t bnfrag_h2(uint32_t a, uint32_t sc2, uint32_t sh2) {
    __half2 r = __hfma2(*(__half2*)&a, *(__half2*)&sc2, *(__half2*)&sh2);
    r = __hmax2(r, __float2half2_rn(0.f));
    return *(uint32_t*)&r;
}

// ---------------- scratch (static device globals) ----------------
__device__ int      g_idx[NROWS];
__device__ float    g_part1[STAT_BLOCKS*2*C1];
__device__ float    g_ss1[2*C1];
__device__ __half   g_Ah[(size_t)NROWS*C1];      // 42 MB
__device__ __half   g_H2h[(size_t)NROWS*C2];     // 84 MB
__device__ __half   g_gmaxh[(size_t)NPTS*C2];
__device__ float    g_fA[(size_t)NPTS*C3];
__device__ __half   g_fpreh[(size_t)NROWS*C3];   // 168 MB
__device__ float    g_p3[(size_t)(NROWS/128)*2*C3];
__device__ float    g_ss3[2*C3];
__device__ uint32_t g_ss3h[2*(C3/2)];            // half2-packed: [sc 256][sh 256]
__device__ uint32_t g_w2h[64*C2];                // W2 packed [k/2][col]
__device__ uint32_t g_w3h[128*C3];               // W3[256:512] packed [k/2][col]
__device__ uint32_t g_w4h[256*CH];               // W4 packed [k/2][col]

// ---------------------------------------------------------------------------
// K1: KNN (unchanged — passing, R9)
// ---------------------------------------------------------------------------
__global__ void knn_kernel(const float* __restrict__ xyz) {
    __shared__ float sd[NN];
    __shared__ float rv[8];
    __shared__ int   ri8[8];
    __shared__ int   swin;
    int p = blockIdx.x;
    int b = p >> 12, n = p & (NN-1);
    int t = threadIdx.x, lane = t & 31, w = t >> 5;
    const float* base = xyz + (size_t)b*NN*3;
    float cx = base[n*3+0], cy = base[n*3+1], cz = base[n*3+2];
    float pp = cx*cx + cy*cy + cz*cz;
    float bv = FLT_MAX; int bi = NN;
    for (int m = t; m < NN; m += 256) {
        float qx = base[m*3+0], qy = base[m*3+1], qz = base[m*3+2];
        float d2 = pp + (qx*qx + qy*qy + qz*qz) - 2.f*(cx*qx + cy*qy + cz*qz);
        sd[m] = d2;
        if (d2 < bv) { bv = d2; bi = m; }
    }
    __syncthreads();
    for (int round = 0; round < KNBR; ++round) {
        float rb = bv; int rx = bi;
        #pragma unroll
        for (int off = 16; off > 0; off >>= 1) {
            float ov = __shfl_down_sync(0xffffffffu, rb, off);
            int   oi = __shfl_down_sync(0xffffffffu, rx, off);
            if (ov < rb || (ov == rb && oi < rx)) { rb = ov; rx = oi; }
        }
        if (lane == 0) { rv[w] = rb; ri8[w] = rx; }
        __syncthreads();
        if (w == 0) {
            float v2 = (lane < 8) ? rv[lane] : FLT_MAX;
            int   i2 = (lane < 8) ? ri8[lane] : NN;
            #pragma unroll
            for (int off = 4; off > 0; off >>= 1) {
                float ov = __shfl_down_sync(0xffffffffu, v2, off);
                int   oi = __shfl_down_sync(0xffffffffu, i2, off);
                if (ov < v2 || (ov == v2 && oi < i2)) { v2 = ov; i2 = oi; }
            }
            if (lane == 0) {
                g_idx[p*KNBR + round] = i2;
                sd[i2] = FLT_MAX;
                swin = i2;
            }
        }
        __syncthreads();
        if (bi == swin) {
            bv = FLT_MAX; bi = NN;
            for (int m = t; m < NN; m += 256) {
                float v = sd[m];
                if (v < bv) { bv = v; bi = m; }
            }
        }
    }
}

// ---------------------------------------------------------------------------
// BN1 stats (unchanged)
// ---------------------------------------------------------------------------
__global__ void stats1_kernel(const float* __restrict__ xyz,
                              const float* __restrict__ W1,
                              const float* __restrict__ b1) {
    __shared__ float se[ROWS_PER_STAT*6];
    int blk = blockIdx.x, t = threadIdx.x;
    int row0 = blk * ROWS_PER_STAT;
    for (int r = t; r < ROWS_PER_STAT; r += 128) {
        int gr = row0 + r;
        int p  = gr / KNBR;
        int b  = p >> 12, n = p & (NN-1);
        int id = g_idx[gr];
        const float* cb = xyz + ((size_t)b*NN + n)*3;
        const float* nb = xyz + ((size_t)b*NN + id)*3;
        se[r*6+0] = nb[0]-cb[0];
        se[r*6+1] = nb[1]-cb[1];
        se[r*6+2] = nb[2]-cb[2];
        se[r*6+3] = cb[0]; se[r*6+4] = cb[1]; se[r*6+5] = cb[2];
    }
    __syncthreads();
    float w0 = W1[0*C1+t], w1 = W1[1*C1+t], w2 = W1[2*C1+t],
          w3 = W1[3*C1+t], w4 = W1[4*C1+t], w5 = W1[5*C1+t], bb = b1[t];
    float s = 0.f, q = 0.f;
    for (int r = 0; r < ROWS_PER_STAT; ++r) {
        float h = bb + se[r*6+0]*w0 + se[r*6+1]*w1 + se[r*6+2]*w2
                     + se[r*6+3]*w3 + se[r*6+4]*w4 + se[r*6+5]*w5;
        s += h; q += h*h;
    }
    g_part1[blk*(2*C1) + t]      = s;
    g_part1[blk*(2*C1) + C1 + t] = q;
}

__global__ void fin1_kernel(const float* __restrict__ g1,
                            const float* __restrict__ be1) {
    int c = threadIdx.x;
    float s = 0.f, q = 0.f;
    for (int i = 0; i < STAT_BLOCKS; ++i) {
        s += g_part1[i*(2*C1)+c];
        q += g_part1[i*(2*C1)+C1+c];
    }
    float mu  = s / (float)NROWS;
    float var = q / (float)NROWS - mu*mu;
    float sc  = g1[c] * rsqrtf(var + BN_EPS);
    g_ss1[c]     = sc;
    g_ss1[C1+c]  = be1[c] - mu*sc;
}

// ---------------------------------------------------------------------------
// edge16: writes fp16 A (unchanged)
// ---------------------------------------------------------------------------
__global__ __launch_bounds__(256) void edge_kernel(
    const float* __restrict__ xyz,
    const float* __restrict__ W1, const float* __restrict__ b1) {
    __shared__ float sE[16*6];
    int row0 = blockIdx.x * 16, t = threadIdx.x;
    if (t < 96) {
        int r = t / 6, d = t - r*6;
        int row = row0 + r;
        int p = row / KNBR;
        int b = p >> 12, n = p & (NN-1);
        float v;
        if (d < 3) {
            int id = g_idx[row];
            v = xyz[((size_t)b*NN + id)*3 + d] - xyz[((size_t)b*NN + n)*3 + d];
        } else {
            v = xyz[((size_t)b*NN + n)*3 + (d-3)];
        }
        sE[r*6 + d] = v;
    }
    __syncthreads();
    int c = t & (C1-1), h = t >> 7;
    float w0 = W1[0*C1+c], w1 = W1[1*C1+c], w2 = W1[2*C1+c],
          w3 = W1[3*C1+c], w4 = W1[4*C1+c], w5 = W1[5*C1+c];
    float bb = b1[c], sc = g_ss1[c], sh = g_ss1[C1+c];
    #pragma unroll
    for (int rr = 0; rr < 8; ++rr) {
        int r = h*8 + rr;
        float hv = bb + sE[r*6+0]*w0 + sE[r*6+1]*w1 + sE[r*6+2]*w2
                      + sE[r*6+3]*w3 + sE[r*6+4]*w4 + sE[r*6+5]*w5;
        hv = fmaxf(hv*sc + sh, 0.f);
        g_Ah[(size_t)(row0 + r)*C1 + c] = __float2half_rn(hv);
    }
}

// ---------------------------------------------------------------------------
// weight prep: half2-packed [k/2][col]
// ---------------------------------------------------------------------------
__global__ void w2h_kernel(const float* __restrict__ W2) {
    int i = blockIdx.x*256 + threadIdx.x;
    if (i < 64*C2) {
        int kp = i / C2, col = i - kp*C2;
        g_w2h[i] = pack_h2(W2[(size_t)(2*kp)*C2 + col],
                           W2[(size_t)(2*kp + 1)*C2 + col]);
    }
}
__global__ void w3h_kernel(const float* __restrict__ W3) {
    int i = blockIdx.x*256 + threadIdx.x;
    if (i < 128*C3) {
        int kp = i / C3, col = i - kp*C3;
        g_w3h[i] = pack_h2(W3[(size_t)(C2 + 2*kp)*C3 + col],
                           W3[(size_t)(C2 + 2*kp + 1)*C3 + col]);
    }
}
__global__ void w4h_kernel(const float* __restrict__ W4) {
    int i = blockIdx.x*256 + threadIdx.x;
    if (i < 256*CH) {
        int kp = i / CH, col = i - kp*CH;
        g_w4h[i] = pack_h2(W4[(size_t)(2*kp)*CH + col],
                           W4[(size_t)(2*kp + 1)*CH + col]);
    }
}

// ===========================================================================
// fp16 m16n8k16 tile configs
// ===========================================================================
#define GM_MT 128
#define GM_MT2 256
#define GM_NT 64
#define GM_KC 32
#define SAH 20
#define SBH 72
#define A_BUFH  (GM_MT*SAH)     // 2560 u32
#define A_BUFH2 (GM_MT2*SAH)    // 5120 u32
#define B_BUFH  (16*SBH)        // 1152 u32

#define MMA_F16(acc, af, bf) \
    asm volatile( \
        "mma.sync.aligned.m16n8k16.row.col.f32.f16.f16.f32 " \
        "{%0,%1,%2,%3}, {%4,%5,%6,%7}, {%8,%9}, {%0,%1,%2,%3};" \
        : "+f"((acc)[0]), "+f"((acc)[1]), "+f"((acc)[2]), "+f"((acc)[3]) \
        : "r"((af)[0]), "r"((af)[1]), "r"((af)[2]), "r"((af)[3]), \
          "r"((bf)[0]), "r"((bf)[1]))

// ---------------------------------------------------------------------------
// gemm2 load helper (256 threads)
// ---------------------------------------------------------------------------
__device__ __forceinline__ void g2_load(uint32_t* A, uint32_t* B,
                                        size_t row0, int n0, int kk, int t) {
    #pragma unroll
    for (int pq = 0; pq < 4; ++pq) {
        int r = pq*64 + (t>>2), seg = t&3;
        cp16(&A[r*SAH + seg*4], g_Ah + (row0 + r)*C1 + kk + seg*8);
    }
    int kp = t>>4, s = t&15;
    int kpg = (kk>>1) + kp;
    cp16(&B[kp*SBH + s*4], &g_w2h[(size_t)kpg*C2 + n0 + s*4]);
}

// ---------------------------------------------------------------------------
// gemm2: H2 = A @ W2 + b2, CTA 256x64 with 256 threads, 3-stage cp.async,
// ldmatrix A, prepacked B. (same math as R14 gemm2 — bit-identical output)
// ---------------------------------------------------------------------------
#define G2_SMEM ((3*A_BUFH2 + 3*B_BUFH)*4)
__global__ __launch_bounds__(256) void gemm2_kernel(const float* __restrict__ b2) {
    extern __shared__ __align__(16) uint32_t dyn[];
    uint32_t* bufA = dyn;
    uint32_t* bufB = dyn + 3*A_BUFH2;
    int t = threadIdx.x;
    int w = t >> 5, lane = t & 31;
    int g = lane >> 2, tig = lane & 3;
    int roff = lane & 15, koff = (lane >> 4) * 4;
    size_t row0 = (size_t)blockIdx.y * GM_MT2;
    int n0 = blockIdx.x * GM_NT;
    uint32_t sbA0 = (uint32_t)__cvta_generic_to_shared(bufA);

    float acc[2][8][4] = {};
    const int NC = C1/GM_KC;  // 4

    g2_load(bufA, bufB, row0, n0, 0, t);                      CP_COMMIT();
    g2_load(bufA + A_BUFH2, bufB + B_BUFH, row0, n0, 32, t);  CP_COMMIT();

    for (int c = 0; c < NC; ++c) {
        int cur = c % 3;
        if (c + 2 < NC) {
            int st = (c+2) % 3;
            g2_load(bufA + st*A_BUFH2, bufB + st*B_BUFH, row0, n0, (c+2)*GM_KC, t);
            CP_COMMIT();
            CP_WAIT(2);
        } else if (c + 1 < NC) {
            CP_WAIT(1);
        } else {
            CP_WAIT(0);
        }
        __syncthreads();

        uint32_t sbA = sbA0 + cur*A_BUFH2*4;
        uint32_t* B = bufB + cur*B_BUFH;
        #pragma unroll
        for (int ks = 0; ks < 2; ++ks) {
            int kb = ks*8;
            uint32_t bf[8][2];
            #pragma unroll
            for (int n = 0; n < 8; ++n) {
                bf[n][0] = B[(kb+tig)*SBH   + n*8 + g];
                bf[n][1] = B[(kb+tig+4)*SBH + n*8 + g];
            }
            #pragma unroll
            for (int m = 0; m < 2; ++m) {
                int mr = w*32 + m*16;
                uint32_t af[4];
                ldsm4(af, sbA + ((mr + roff)*SAH + kb + koff)*4);
                #pragma unroll
                for (int n = 0; n < 8; ++n) MMA_F16(acc[m][n], af, bf[n]);
            }
        }
        __syncthreads();
    }
    uint32_t* H2v = (uint32_t*)g_H2h;
    #pragma unroll
    for (int m = 0; m < 2; ++m) {
        size_t r0 = row0 + w*32 + m*16 + g;
        #pragma unroll
        for (int n = 0; n < 8; ++n) {
            int col = n0 + n*8 + 2*tig;
            float2 bb = *(const float2*)&b2[col];
            H2v[r0*(C2/2) + col/2]     = pack_h2(acc[m][n][0]+bb.x, acc[m][n][1]+bb.y);
            H2v[(r0+8)*(C2/2) + col/2] = pack_h2(acc[m][n][2]+bb.x, acc[m][n][3]+bb.y);
        }
    }
}

// ---------------------------------------------------------------------------
// gmax over fp16 pairs (unchanged)
// ---------------------------------------------------------------------------
__global__ void gmax_kernel() {
    int p = blockIdx.x, t = threadIdx.x;   // 128 threads
    const __half2* src = (const __half2*)g_H2h + (size_t)p*KNBR*(C2/2) + t;
    __half2 m = src[0];
    #pragma unroll
    for (int r = 1; r < KNBR; ++r) m = __hmax2(m, src[(size_t)r*(C2/2)]);
    ((__half2*)g_gmaxh)[(size_t)p*(C2/2) + t] = m;
}

// ---------------------------------------------------------------------------
// gemmFA: fA = gmax @ W3[0:256] + b3 (unchanged from R14)
// ---------------------------------------------------------------------------
__global__ __launch_bounds__(128) void gemmFA_kernel(
    const float* __restrict__ W3, const float* __restrict__ b3) {
    __shared__ __align__(16) uint32_t sA[GM_MT*SAH];
    __shared__ __align__(16) uint32_t sB[16*SBH];
    int t = threadIdx.x;
    int w = t >> 5, lane = t & 31;
    int g = lane >> 2, tig = lane & 3;
    size_t row0 = (size_t)blockIdx.y * GM_MT;
    int n0 = blockIdx.x * GM_NT;

    float acc[2][8][4] = {};

    for (int kk = 0; kk < C2; kk += GM_KC) {
        #pragma unroll
        for (int pq = 0; pq < 4; ++pq) {
            int r = pq*32 + (t>>2), seg = t&3;
            uint4 v = *(const uint4*)(g_gmaxh + (row0 + r)*C2 + kk + seg*8);
            *(uint4*)&sA[r*SAH + seg*4] = v;
        }
        #pragma unroll
        for (int pq = 0; pq < 2; ++pq) {
            int kp = pq*8 + (t>>4), colb = (t&15)*4;
            const float* s0 = &W3[(size_t)(kk + 2*kp)*C3 + n0 + colb];
            float4 va = *(const float4*)s0;
            float4 vb = *(const float4*)(s0 + C3);
            uint4 o = make_uint4(pack_h2(va.x, vb.x), pack_h2(va.y, vb.y),
                                 pack_h2(va.z, vb.z), pack_h2(va.w, vb.w));
            *(uint4*)&sB[kp*SBH + colb] = o;
        }
        __syncthreads();
        #pragma unroll
        for (int ks = 0; ks < 2; ++ks) {
            int kb = ks*8;
            uint32_t bf[8][2];
            #pragma unroll
            for (int n = 0; n < 8; ++n) {
                bf[n][0] = sB[(kb+tig)*SBH   + n*8 + g];
                bf[n][1] = sB[(kb+tig+4)*SBH + n*8 + g];
            }
            #pragma unroll
            for (int m = 0; m < 2; ++m) {
                int mr = w*32 + m*16;
                uint32_t af[4];
                af[0] = sA[(mr+g)*SAH   + kb + tig];
                af[1] = sA[(mr+g+8)*SAH + kb + tig];
                af[2] = sA[(mr+g)*SAH   + kb + tig + 4];
                af[3] = sA[(mr+g+8)*SAH + kb + tig + 4];
                #pragma unroll
                for (int n = 0; n < 8; ++n) MMA_F16(acc[m][n], af, bf[n]);
            }
        }
        __syncthreads();
    }
    #pragma unroll
    for (int m = 0; m < 2; ++m) {
        size_t r0 = row0 + w*32 + m*16 + g;
        #pragma unroll
        for (int n = 0; n < 8; ++n) {
            int col = n0 + n*8 + 2*tig;
            float2 bb = *(const float2*)&b3[col];
            *(float2*)&g_fA[r0*C3 + col]     = make_float2(acc[m][n][0]+bb.x, acc[m][n][1]+bb.y);
            *(float2*)&g_fA[(r0+8)*C3 + col] = make_float2(acc[m][n][2]+bb.x, acc[m][n][3]+bb.y);
        }
    }
}

// ---------------------------------------------------------------------------
// big-GEMM load helpers (256 threads, unchanged from R14)
// ---------------------------------------------------------------------------
__device__ __forceinline__ void g3_load(uint32_t* A, uint32_t* B,
                                        size_t row0, int n0, int kk, int t) {
    #pragma unroll
    for (int pq = 0; pq < 4; ++pq) {
        int r = pq*64 + (t>>2), seg = t&3;
        cp16(&A[r*SAH + seg*4], g_H2h + (row0 + r)*C2 + kk + seg*8);
    }
    int kp = t>>4, s = t&15;
    int kpg = (kk>>1) + kp;
    cp16(&B[kp*SBH + s*4], &g_w3h[(size_t)kpg*C3 + n0 + s*4]);
}
__device__ __forceinline__ void g4_load(uint32_t* A, uint32_t* B,
                                        size_t row0, int n0, int kk, int t) {
    #pragma unroll
    for (int pq = 0; pq < 4; ++pq) {
        int r = pq*64 + (t>>2), seg = t&3;
        cp16(&A[r*SAH + seg*4], g_fpreh + (row0 + r)*C3 + kk + seg*8);
    }
    int kp = t>>4, s = t&15;
    int kpg = (kk>>1) + kp;
    cp16(&B[kp*SBH + s*4], &g_w4h[(size_t)kpg*CH + n0 + s*4]);
}

// ---------------------------------------------------------------------------
// gemm3 (unchanged from R14 — passing)
// ---------------------------------------------------------------------------
#define G3_SMEM ((3*A_BUFH2 + 3*B_BUFH + 1024)*4)
__global__ __launch_bounds__(256) void gemm3_kernel() {
    extern __shared__ __align__(16) uint32_t dyn[];
    uint32_t* bufA = dyn;
    uint32_t* bufB = dyn + 3*A_BUFH2;
    float* sstat = (float*)(dyn + 3*A_BUFH2 + 3*B_BUFH);
    int t = threadIdx.x;
    int w = t >> 5, lane = t & 31;
    int g = lane >> 2, tig = lane & 3;
    int roff = lane & 15, koff = (lane >> 4) * 4;
    size_t row0 = (size_t)blockIdx.y * GM_MT2;
    int n0 = blockIdx.x * GM_NT;
    uint32_t sbA0 = (uint32_t)__cvta_generic_to_shared(bufA);

    float acc[2][8][4] = {};
    const int NC = C2/GM_KC;  // 8

    g3_load(bufA, bufB, row0, n0, 0, t);                      CP_COMMIT();
    g3_load(bufA + A_BUFH2, bufB + B_BUFH, row0, n0, 32, t);  CP_COMMIT();

    for (int c = 0; c < NC; ++c) {
        int cur = c % 3;
        if (c + 2 < NC) {
            int st = (c+2) % 3;
            g3_load(bufA + st*A_BUFH2, bufB + st*B_BUFH, row0, n0, (c+2)*GM_KC, t);
            CP_COMMIT();
            CP_WAIT(2);
        } else if (c + 1 < NC) {
            CP_WAIT(1);
        } else {
            CP_WAIT(0);
        }
        __syncthreads();

        uint32_t sbA = sbA0 + cur*A_BUFH2*4;
        uint32_t* B = bufB + cur*B_BUFH;
        #pragma unroll
        for (int ks = 0; ks < 2; ++ks) {
            int kb = ks*8;
            uint32_t bf[8][2];
            #pragma unroll
            for (int n = 0; n < 8; ++n) {
                bf[n][0] = B[(kb+tig)*SBH   + n*8 + g];
                bf[n][1] = B[(kb+tig+4)*SBH + n*8 + g];
            }
            #pragma unroll
            for (int m = 0; m < 2; ++m) {
                int mr = w*32 + m*16;
                uint32_t af[4];
                ldsm4(af, sbA + ((mr + roff)*SAH + kb + koff)*4);
                #pragma unroll
                for (int n = 0; n < 8; ++n) MMA_F16(acc[m][n], af, bf[n]);
            }
        }
        __syncthreads();
    }

    uint32_t* FPv = (uint32_t*)g_fpreh;
    float sloc[8][2], qloc[8][2];
    #pragma unroll
    for (int n = 0; n < 8; ++n) { sloc[n][0]=0.f; sloc[n][1]=0.f; qloc[n][0]=0.f; qloc[n][1]=0.f; }
    #pragma unroll
    for (int m = 0; m < 2; ++m) {
        size_t rA = row0 + w*32 + m*16 + g;
        size_t rB = rA + 8;
        size_t pA = rA / KNBR, pB = rB / KNBR;
        #pragma unroll
        for (int n = 0; n < 8; ++n) {
            int col = n0 + n*8 + 2*tig;
            float2 fa = *(const float2*)&g_fA[pA*C3 + col];
            float2 fb = *(const float2*)&g_fA[pB*C3 + col];
            float v0 = acc[m][n][0]+fa.x, v1 = acc[m][n][1]+fa.y;
            float v2 = acc[m][n][2]+fb.x, v3 = acc[m][n][3]+fb.y;
            FPv[rA*(C3/2) + col/2] = pack_h2(v0, v1);
            FPv[rB*(C3/2) + col/2] = pack_h2(v2, v3);
            sloc[n][0] += v0 + v2;   qloc[n][0] += v0*v0 + v2*v2;
            sloc[n][1] += v1 + v3;   qloc[n][1] += v1*v1 + v3*v3;
        }
    }
    #pragma unroll
    for (int n = 0; n < 8; ++n)
        #pragma unroll
        for (int j = 0; j < 2; ++j) {
            float s = sloc[n][j], q = qloc[n][j];
            #pragma unroll
            for (int mk = 4; mk <= 16; mk <<= 1) {
                s += __shfl_xor_sync(0xffffffffu, s, mk);
                q += __shfl_xor_sync(0xffffffffu, q, mk);
            }
            if (g == 0) {
                int ci = n*8 + 2*tig + j;
                sstat[(w*64 + ci)*2 + 0] = s;
                sstat[(w*64 + ci)*2 + 1] = q;
            }
        }
    __syncthreads();
    if (t < 128) {
        int ci = t >> 1, which = t & 1;
        float v = 0.f;
        #pragma unroll
        for (int ww = 0; ww < 8; ++ww) v += sstat[(ww*64+ci)*2+which];
        g_p3[(size_t)blockIdx.y*(2*C3) + (size_t)which*C3 + n0 + ci] = v;
    }
}

// ---------------------------------------------------------------------------
// fin3 (unchanged)
// ---------------------------------------------------------------------------
__global__ void fin3_kernel(const float* __restrict__ g3,
                            const float* __restrict__ be3) {
    __shared__ float tmp[2*C3];
    int c = threadIdx.x;   // 512
    float s = 0.f, q = 0.f;
    for (int i = 0; i < NROWS/GM_MT2; ++i) {
        s += g_p3[(size_t)i*(2*C3) + c];
        q += g_p3[(size_t)i*(2*C3) + C3 + c];
    }
    float mu  = s / (float)NROWS;
    float var = q / (float)NROWS - mu*mu;
    float sc  = g3[c] * rsqrtf(var + BN_EPS);
    float sh  = be3[c] - mu*sc;
    g_ss3[c]    = sc;
    g_ss3[C3+c] = sh;
    tmp[c] = sc; tmp[C3+c] = sh;
    __syncthreads();
    if (c < C3/2) {
        g_ss3h[c]          = pack_h2(tmp[2*c],      tmp[2*c+1]);
        g_ss3h[C3/2 + c]   = pack_h2(tmp[C3+2*c],   tmp[C3+2*c+1]);
    }
}

// ---------------------------------------------------------------------------
// init keys
// ---------------------------------------------------------------------------
__global__ void initkeys_kernel(unsigned* __restrict__ keys) {
    int i = blockIdx.x*256 + threadIdx.x;
    if (i < NPTS*CH) keys[i] = 0u;
}

// ---------------------------------------------------------------------------
// gemm_final (unchanged from R14 — passing)
// ---------------------------------------------------------------------------
#define GF_SMEM ((3*A_BUFH2 + 3*B_BUFH + 512)*4)
__global__ __launch_bounds__(256) void gemm_final_kernel(unsigned* __restrict__ keys) {
    extern __shared__ __align__(16) uint32_t dyn[];
    uint32_t* bufA = dyn;
    uint32_t* bufB = dyn + 3*A_BUFH2;
    uint32_t* sSh = dyn + 3*A_BUFH2 + 3*B_BUFH;
    int t = threadIdx.x;
    int w = t >> 5, lane = t & 31;
    int g = lane >> 2, tig = lane & 3;
    int roff = lane & 15, koff = (lane >> 4) * 4;
    size_t row0 = (size_t)blockIdx.y * GM_MT2;
    int n0 = blockIdx.x * GM_NT;
    uint32_t sbA0 = (uint32_t)__cvta_generic_to_shared(bufA);

    float acc[2][8][4] = {};
    const int NC = C3/GM_KC;  // 16

    for (int i = t; i < 2*(C3/2); i += 256) sSh[i] = g_ss3h[i];

    g4_load(bufA, bufB, row0, n0, 0, t);                      CP_COMMIT();
    g4_load(bufA + A_BUFH2, bufB + B_BUFH, row0, n0, 32, t);  CP_COMMIT();

    for (int c = 0; c < NC; ++c) {
        int cur = c % 3;
        if (c + 2 < NC) {
            int st = (c+2) % 3;
            g4_load(bufA + st*A_BUFH2, bufB + st*B_BUFH, row0, n0, (c+2)*GM_KC, t);
            CP_COMMIT();
            CP_WAIT(2);
        } else if (c + 1 < NC) {
            CP_WAIT(1);
        } else {
            CP_WAIT(0);
        }
        __syncthreads();

        uint32_t sbA = sbA0 + cur*A_BUFH2*4;
        uint32_t* B = bufB + cur*B_BUFH;
        int kk = c*GM_KC;
        #pragma unroll
        for (int ks = 0; ks < 2; ++ks) {
            int kb = ks*8;
            int kpg0 = (kk>>1) + kb + tig;
            uint32_t sc0 = sSh[kpg0],     sh0 = sSh[C3/2 + kpg0];
            uint32_t sc4 = sSh[kpg0 + 4], sh4 = sSh[C3/2 + kpg0 + 4];
            uint32_t bf[8][2];
            #pragma unroll
            for (int n = 0; n < 8; ++n) {
                bf[n][0] = B[(kb+tig)*SBH   + n*8 + g];
                bf[n][1] = B[(kb+tig+4)*SBH + n*8 + g];
            }
            #pragma unroll
            for (int m = 0; m < 2; ++m) {
                int mr = w*32 + m*16;
                uint32_t af[4];
                ldsm4(af, sbA + ((mr + roff)*SAH + kb + koff)*4);
                af[0] = bnfrag_h2(af[0], sc0, sh0);
                af[1] = bnfrag_h2(af[1], sc0, sh0);
                af[2] = bnfrag_h2(af[2], sc4, sh4);
                af[3] = bnfrag_h2(af[3], sc4, sh4);
                #pragma unroll
                for (int n = 0; n < 8; ++n) MMA_F16(acc[m][n], af, bf[n]);
            }
        }
        __syncthreads();
    }

    #pragma unroll
    for (int n = 0; n < 8; ++n) {
        #pragma unroll
        for (int cc = 0; cc < 2; ++cc) {
            int col = n0 + n*8 + 2*tig + cc;
            size_t curp = (row0 + w*32 + g) / KNBR;
            float rm = -FLT_MAX;
            #pragma unroll
            for (int j = 0; j < 4; ++j) {
                size_t row = row0 + w*32 + g + 8*j;
                size_t pj = row / KNBR;
                float v = acc[j>>1][n][((j&1)<<1) + cc];
                if (pj != curp) {
                    atomicMax(&keys[curp*CH + col], fenc(rm));
                    curp = pj; rm = v;
                } else {
                    rm = fmaxf(rm, v);
                }
            }
            atomicMax(&keys[curp*CH + col], fenc(rm));
        }
    }
}

// ---------------------------------------------------------------------------
// finish: decode keys + add b4, and copy xyz (merged)
// ---------------------------------------------------------------------------
__global__ void finish_kernel(float* __restrict__ out,
                              const float* __restrict__ b4,
                              const float* __restrict__ xyz) {
    int i = blockIdx.x*256 + threadIdx.x;
    if (i < NPTS*CH) {
        int c = i % CH;
        unsigned k = ((const unsigned*)(out + (size_t)BB*NN*3))[i];
        out[(size_t)BB*NN*3 + i] = fdec(k) + b4[c];
    }
    if (i < BB*NN*3) out[i] = xyz[i];
}

extern "C" void kernel_launch(void* const* d_in, const int* in_sizes, int n_in,
                              void* d_out, int out_size) {
    (void)in_sizes; (void)n_in; (void)out_size;
    const float* xyz = (const float*)d_in[0];
    const float* W1  = (const float*)d_in[1];
    const float* b1  = (const float*)d_in[2];
    const float* g1  = (const float*)d_in[3];
    const float* be1 = (const float*)d_in[4];
    const float* W2  = (const float*)d_in[5];
    const float* b2  = (const float*)d_in[6];
    const float* W3  = (const float*)d_in[7];
    const float* b3  = (const float*)d_in[8];
    const float* g3  = (const float*)d_in[9];
    const float* be3 = (const float*)d_in[10];
    const float* W4  = (const float*)d_in[11];
    const float* b4  = (const float*)d_in[12];
    float* out = (float*)d_out;
    unsigned* keys = (unsigned*)(out + (size_t)BB*NN*3);

    static int smem_set = 0;
    if (!smem_set) {
        cudaFuncSetAttribute(gemm2_kernel, cudaFuncAttributeMaxDynamicSharedMemorySize, G2_SMEM);
        cudaFuncSetAttribute(gemm3_kernel, cudaFuncAttributeMaxDynamicSharedMemorySize, G3_SMEM);
        cudaFuncSetAttribute(gemm_final_kernel, cudaFuncAttributeMaxDynamicSharedMemorySize, GF_SMEM);
        smem_set = 1;
    }

    knn_kernel<<<NPTS, 256>>>(xyz);
    stats1_kernel<<<STAT_BLOCKS, 128>>>(xyz, W1, b1);
    fin1_kernel<<<1, C1>>>(g1, be1);
    edge_kernel<<<NROWS/16, 256>>>(xyz, W1, b1);
    w2h_kernel<<<(64*C2 + 255)/256, 256>>>(W2);
    w3h_kernel<<<(128*C3 + 255)/256, 256>>>(W3);
    w4h_kernel<<<(256*CH + 255)/256, 256>>>(W4);
    {
        dim3 grid2(C2/GM_NT, NROWS/GM_MT2);  // (4, 640)
        gemm2_kernel<<<grid2, 256, G2_SMEM>>>(b2);
    }
    gmax_kernel<<<NPTS, 128>>>();
    {
        dim3 gridFA(C3/GM_NT, NPTS/GM_MT);   // (8, 64)
        gemmFA_kernel<<<gridFA, 128>>>(W3, b3);
    }
    {
        dim3 grid3(C3/GM_NT, NROWS/GM_MT2);  // (8, 640)
        gemm3_kernel<<<grid3, 256, G3_SMEM>>>();
    }
    fin3_kernel<<<1, C3>>>(g3, be3);
    initkeys_kernel<<<(NPTS*CH + 255)/256, 256>>>(keys);
    {
        dim3 grid4(CH/GM_NT, NROWS/GM_MT2);  // (6, 640)
        gemm_final_kernel<<<grid4, 256, GF_SMEM>>>(keys);
    }
    finish_kernel<<<(NPTS*CH + 255)/256, 256>>>(out, b4, xyz);
}